// round 1
// baseline (speedup 1.0000x reference)
#include <cuda_runtime.h>
#include <math_constants.h>

// ---------------------------------------------------------------------------
// MultiHeadAttention (block-local), fp32 baseline.
//   q = (x @ Wq.T + bq) * hd^-0.25
//   k = (x @ Wk.T)      * hd^-0.25
//   v =  x @ Wv.T + bv
//   per (b, block, head): S = q k^T ; P = softmax(S) ; O = P v
//   out = att @ Wo.T + bo
// Shapes: B=4, T=4096, C=1024, H=16, HD=64, NBLOCKS=32, BSIZE=128
// ---------------------------------------------------------------------------

#define M_ROWS 16384      // B*T
#define CDIM   1024
#define QK_SCALE 0.35355339059327376f   // 64^(-0.25)

// scratch (no cudaMalloc allowed)
__device__ float g_q[M_ROWS * CDIM];
__device__ float g_k[M_ROWS * CDIM];
__device__ float g_v[M_ROWS * CDIM];
__device__ float g_att[M_ROWS * CDIM];

// ---------------------------------------------------------------------------
// SGEMM (NT): C[M,N] = alpha * (A[M,K] @ W[N,K]^T + bias[N])
// 128x128 tile, BK=8, 256 threads, 8x8 register microtile per thread.
// All dims are multiples of the tile sizes (no bounds checks needed).
// ---------------------------------------------------------------------------
__global__ __launch_bounds__(256, 2)
void sgemm_nt_bias(const float* __restrict__ A,
                   const float* __restrict__ W,
                   const float* __restrict__ bias,
                   float* __restrict__ C,
                   int K, int N, float alpha)
{
    __shared__ float As[8][128];
    __shared__ float Bs[8][128];

    const int tid = threadIdx.x;
    const int tx = tid & 15;          // 0..15 -> 8 cols each
    const int ty = tid >> 4;          // 0..15 -> 8 rows each
    const int rowBase = blockIdx.y * 128;
    const int colBase = blockIdx.x * 128;

    // cooperative load mapping: 256 threads -> 128 rows x 2 float4 of K
    const int lr = tid >> 1;              // 0..127
    const int lk = (tid & 1) << 2;        // 0 or 4

    const float* Ap = A + (size_t)(rowBase + lr) * K + lk;
    const float* Wp = W + (size_t)(colBase + lr) * K + lk;

    float acc[8][8];
#pragma unroll
    for (int i = 0; i < 8; i++)
#pragma unroll
        for (int j = 0; j < 8; j++) acc[i][j] = 0.f;

    for (int k0 = 0; k0 < K; k0 += 8) {
        const float4 a4 = *(const float4*)(Ap + k0);
        const float4 w4 = *(const float4*)(Wp + k0);
        __syncthreads();   // previous compute done before overwriting smem
        As[lk + 0][lr] = a4.x; As[lk + 1][lr] = a4.y;
        As[lk + 2][lr] = a4.z; As[lk + 3][lr] = a4.w;
        Bs[lk + 0][lr] = w4.x; Bs[lk + 1][lr] = w4.y;
        Bs[lk + 2][lr] = w4.z; Bs[lk + 3][lr] = w4.w;
        __syncthreads();

#pragma unroll
        for (int k = 0; k < 8; k++) {
            float ar[8], br[8];
            *(float4*)(ar)     = *(const float4*)(&As[k][ty * 8]);
            *(float4*)(ar + 4) = *(const float4*)(&As[k][ty * 8 + 4]);
            *(float4*)(br)     = *(const float4*)(&Bs[k][tx * 8]);
            *(float4*)(br + 4) = *(const float4*)(&Bs[k][tx * 8 + 4]);
#pragma unroll
            for (int i = 0; i < 8; i++)
#pragma unroll
                for (int j = 0; j < 8; j++)
                    acc[i][j] = fmaf(ar[i], br[j], acc[i][j]);
        }
    }

    float bj[8];
#pragma unroll
    for (int j = 0; j < 8; j++)
        bj[j] = bias ? bias[colBase + tx * 8 + j] : 0.f;

#pragma unroll
    for (int i = 0; i < 8; i++) {
        float* Cp = C + (size_t)(rowBase + ty * 8 + i) * N + colBase + tx * 8;
        float4 o0, o1;
        o0.x = alpha * (acc[i][0] + bj[0]);
        o0.y = alpha * (acc[i][1] + bj[1]);
        o0.z = alpha * (acc[i][2] + bj[2]);
        o0.w = alpha * (acc[i][3] + bj[3]);
        o1.x = alpha * (acc[i][4] + bj[4]);
        o1.y = alpha * (acc[i][5] + bj[5]);
        o1.z = alpha * (acc[i][6] + bj[6]);
        o1.w = alpha * (acc[i][7] + bj[7]);
        *(float4*)(Cp)     = o0;
        *(float4*)(Cp + 4) = o1;
    }
}

// ---------------------------------------------------------------------------
// Block-local attention. One CTA per (b, block, head).
// smem (dynamic, 133120 B):
//   [0      : 8192)  q_s [128][64]   (natural)   -- reused for v_s in phase B
//   [8192   : 16384) kT  [64][128]   (transposed)
//   [16384  : 33280) S   [128][132]  (padded rows, scores -> probs)
// ---------------------------------------------------------------------------
#define ATTN_SMEM_FLOATS (8192 + 8192 + 128 * 132)
#define ATTN_SMEM_BYTES  (ATTN_SMEM_FLOATS * 4)

__global__ __launch_bounds__(256)
void block_attn(const float* __restrict__ Q, const float* __restrict__ K,
                const float* __restrict__ V, float* __restrict__ O)
{
    extern __shared__ float sm[];
    float* q_s = sm;                 // [128][64]
    float* kT  = sm + 8192;          // [64][128]
    float* S   = sm + 16384;         // [128][132]
    float* v_s = sm;                 // aliases q_s (reused after phase A)

    __shared__ float redm[256];
    __shared__ float reds[256];

    const int tid = threadIdx.x;
    const int idx = blockIdx.x;
    const int h = idx & 15;
    const int n = (idx >> 4) & 31;
    const int b = idx >> 9;
    const size_t base = ((size_t)b * 4096 + (size_t)n * 128) * 1024 + (size_t)h * 64;

    // load q (natural) and k (transposed) tiles
    for (int i = tid; i < 128 * 16; i += 256) {
        const int r  = i >> 4;
        const int c4 = (i & 15) << 2;
        const float4 qv = *(const float4*)(Q + base + (size_t)r * 1024 + c4);
        *(float4*)(q_s + r * 64 + c4) = qv;
        const float4 kv = *(const float4*)(K + base + (size_t)r * 1024 + c4);
        kT[(c4 + 0) * 128 + r] = kv.x;
        kT[(c4 + 1) * 128 + r] = kv.y;
        kT[(c4 + 2) * 128 + r] = kv.z;
        kT[(c4 + 3) * 128 + r] = kv.w;
    }
    __syncthreads();

    // ---- phase A: S[128][128] = q @ k^T (scale pre-applied in projections)
    {
        const int tx = tid & 15, ty = tid >> 4;
        float acc[8][8];
#pragma unroll
        for (int i = 0; i < 8; i++)
#pragma unroll
            for (int j = 0; j < 8; j++) acc[i][j] = 0.f;

        for (int d = 0; d < 64; d++) {
            float ar[8], br[8];
#pragma unroll
            for (int i = 0; i < 8; i++) ar[i] = q_s[(ty * 8 + i) * 64 + d];
            *(float4*)(br)     = *(const float4*)(kT + d * 128 + tx * 8);
            *(float4*)(br + 4) = *(const float4*)(kT + d * 128 + tx * 8 + 4);
#pragma unroll
            for (int i = 0; i < 8; i++)
#pragma unroll
                for (int j = 0; j < 8; j++)
                    acc[i][j] = fmaf(ar[i], br[j], acc[i][j]);
        }
#pragma unroll
        for (int i = 0; i < 8; i++)
#pragma unroll
            for (int j = 0; j < 8; j++)
                S[(ty * 8 + i) * 132 + tx * 8 + j] = acc[i][j];
    }
    __syncthreads();   // S complete; q_s no longer read

    // load v into v_s (aliases q_s — safe after the barrier above)
    for (int i = tid; i < 128 * 16; i += 256) {
        const int r  = i >> 4;
        const int c4 = (i & 15) << 2;
        *(float4*)(v_s + r * 64 + c4) =
            *(const float4*)(V + base + (size_t)r * 1024 + c4);
    }

    // ---- softmax over rows of S: 2 threads per row (64 cols each)
    {
        const int r = tid >> 1;
        float* Srow = S + r * 132 + (tid & 1) * 64;
        float m = -CUDART_INF_F;
#pragma unroll 8
        for (int j = 0; j < 64; j++) m = fmaxf(m, Srow[j]);
        redm[tid] = m;
        __syncthreads();   // also orders the v_s stores above
        m = fmaxf(redm[r * 2], redm[r * 2 + 1]);
        float s = 0.f;
#pragma unroll 8
        for (int j = 0; j < 64; j++) {
            const float e = __expf(Srow[j] - m);
            Srow[j] = e;
            s += e;
        }
        reds[tid] = s;
        __syncthreads();
        const float inv = 1.f / (reds[r * 2] + reds[r * 2 + 1]);
#pragma unroll 8
        for (int j = 0; j < 64; j++) Srow[j] *= inv;
    }
    __syncthreads();

    // ---- phase B: O[128][64] = P @ V  (32 rows-of-4 x 8 cols-of-8 microtiles)
    {
        const int txb = tid & 7;    // 8 cols each
        const int tyb = tid >> 3;   // 4 rows each
        float acc[4][8];
#pragma unroll
        for (int i = 0; i < 4; i++)
#pragma unroll
            for (int j = 0; j < 8; j++) acc[i][j] = 0.f;

        for (int jj = 0; jj < 128; jj++) {
            float ar[4], br[8];
#pragma unroll
            for (int i = 0; i < 4; i++) ar[i] = S[(tyb * 4 + i) * 132 + jj];
            *(float4*)(br)     = *(const float4*)(v_s + jj * 64 + txb * 8);
            *(float4*)(br + 4) = *(const float4*)(v_s + jj * 64 + txb * 8 + 4);
#pragma unroll
            for (int i = 0; i < 4; i++)
#pragma unroll
                for (int j = 0; j < 8; j++)
                    acc[i][j] = fmaf(ar[i], br[j], acc[i][j]);
        }

#pragma unroll
        for (int i = 0; i < 4; i++) {
            float* Op = O + base + (size_t)(tyb * 4 + i) * 1024 + txb * 8;
            float4 o0, o1;
            o0.x = acc[i][0]; o0.y = acc[i][1]; o0.z = acc[i][2]; o0.w = acc[i][3];
            o1.x = acc[i][4]; o1.y = acc[i][5]; o1.z = acc[i][6]; o1.w = acc[i][7];
            *(float4*)(Op)     = o0;
            *(float4*)(Op + 4) = o1;
        }
    }
}

// ---------------------------------------------------------------------------
extern "C" void kernel_launch(void* const* d_in, const int* in_sizes, int n_in,
                              void* d_out, int out_size)
{
    const float* x  = (const float*)d_in[0];
    const float* Wq = (const float*)d_in[1];
    const float* bq = (const float*)d_in[2];
    const float* Wk = (const float*)d_in[3];
    const float* Wv = (const float*)d_in[4];
    const float* bv = (const float*)d_in[5];
    const float* Wo = (const float*)d_in[6];
    const float* bo = (const float*)d_in[7];
    float* out = (float*)d_out;

    float *q, *k, *v, *att;
    cudaGetSymbolAddress((void**)&q,   g_q);
    cudaGetSymbolAddress((void**)&k,   g_k);
    cudaGetSymbolAddress((void**)&v,   g_v);
    cudaGetSymbolAddress((void**)&att, g_att);

    cudaFuncSetAttribute(block_attn,
                         cudaFuncAttributeMaxDynamicSharedMemorySize,
                         ATTN_SMEM_BYTES);

    const dim3 grid(CDIM / 128, M_ROWS / 128);   // (8, 128)
    const dim3 blk(256);

    // projections (scale baked into q and k)
    sgemm_nt_bias<<<grid, blk>>>(x, Wq, bq,      q,   CDIM, CDIM, QK_SCALE);
    sgemm_nt_bias<<<grid, blk>>>(x, Wk, nullptr, k,   CDIM, CDIM, QK_SCALE);
    sgemm_nt_bias<<<grid, blk>>>(x, Wv, bv,      v,   CDIM, CDIM, 1.0f);

    // block-local attention: 4 * 32 * 16 = 2048 tiles
    block_attn<<<2048, 256, ATTN_SMEM_BYTES>>>(q, k, v, att);

    // output projection
    sgemm_nt_bias<<<grid, blk>>>(att, Wo, bo, out, CDIM, CDIM, 1.0f);
}

// round 4
// speedup vs baseline: 2.6976x; 2.6976x over previous
#include <cuda_runtime.h>
#include <cuda_bf16.h>
#include <math_constants.h>
#include <cstdint>

// ---------------------------------------------------------------------------
// MultiHeadAttention (block-local).
// GEMMs: warp-level HMMA (mma.sync m16n8k16 bf16) with bf16x3 fp32 emulation.
// (tcgen05 unavailable: harness compiles PTX for compute_103 non-'a'.)
// Shapes: B=4, T=4096, C=1024, H=16, HD=64, NBLOCKS=32, BSIZE=128
// ---------------------------------------------------------------------------

#define M_ROWS 16384
#define CDIM   1024
#define QK_SCALE 0.35355339059327376f   // 64^(-0.25)

// fp32 scratch
__device__ __align__(256) float g_q[M_ROWS * CDIM];
__device__ __align__(256) float g_k[M_ROWS * CDIM];
__device__ __align__(256) float g_v[M_ROWS * CDIM];
__device__ __align__(256) float g_att[M_ROWS * CDIM];
// bf16 hi/lo splits
__device__ __align__(256) __nv_bfloat16 g_xh[M_ROWS * CDIM];
__device__ __align__(256) __nv_bfloat16 g_xl[M_ROWS * CDIM];
__device__ __align__(256) __nv_bfloat16 g_ah[M_ROWS * CDIM];
__device__ __align__(256) __nv_bfloat16 g_al[M_ROWS * CDIM];
__device__ __align__(256) __nv_bfloat16 g_wh[4 * CDIM * CDIM];
__device__ __align__(256) __nv_bfloat16 g_wl[4 * CDIM * CDIM];

// ---------------------------------------------------------------------------
// helpers
// ---------------------------------------------------------------------------
__device__ __forceinline__ uint32_t smem_u32(const void* p) {
    uint32_t a;
    asm("{ .reg .u64 t; cvta.to.shared.u64 t, %1; cvt.u32.u64 %0, t; }"
        : "=r"(a) : "l"(p));
    return a;
}

__device__ __forceinline__ void cp_async16(uint32_t dst, const void* src) {
    asm volatile("cp.async.cg.shared.global [%0], [%1], 16;"
                 :: "r"(dst), "l"(src));
}
#define CP_COMMIT() asm volatile("cp.async.commit_group;" ::: "memory")
#define CP_WAIT(n)  asm volatile("cp.async.wait_group %0;" :: "n"(n) : "memory")

__device__ __forceinline__ void ldsm4(uint32_t addr, uint32_t& r0, uint32_t& r1,
                                      uint32_t& r2, uint32_t& r3) {
    asm volatile("ldmatrix.sync.aligned.m8n8.x4.shared.b16 {%0,%1,%2,%3}, [%4];"
                 : "=r"(r0), "=r"(r1), "=r"(r2), "=r"(r3) : "r"(addr));
}

__device__ __forceinline__ void mma16816(float* d, const uint32_t* a,
                                         const uint32_t* b) {
    asm volatile(
        "mma.sync.aligned.m16n8k16.row.col.f32.bf16.bf16.f32 "
        "{%0,%1,%2,%3}, {%4,%5,%6,%7}, {%8,%9}, {%0,%1,%2,%3};"
        : "+f"(d[0]), "+f"(d[1]), "+f"(d[2]), "+f"(d[3])
        : "r"(a[0]), "r"(a[1]), "r"(a[2]), "r"(a[3]), "r"(b[0]), "r"(b[1]));
}

__device__ __forceinline__ uint32_t swz(uint32_t off) {
    return off ^ ((off >> 3) & 0x70);
}

// ---------------------------------------------------------------------------
// fp32 -> bf16 hi/lo split
// ---------------------------------------------------------------------------
__global__ void split_hi_lo(const float* __restrict__ x,
                            __nv_bfloat16* __restrict__ h,
                            __nv_bfloat16* __restrict__ l, int n)
{
    int i = (blockIdx.x * 256 + threadIdx.x) * 4;
    if (i >= n) return;
    float4 v = *(const float4*)(x + i);
    float f[4] = {v.x, v.y, v.z, v.w};
    __nv_bfloat16 hh[4], ll[4];
#pragma unroll
    for (int j = 0; j < 4; j++) {
        hh[j] = __float2bfloat16_rn(f[j]);
        ll[j] = __float2bfloat16_rn(f[j] - __bfloat162float(hh[j]));
    }
    __nv_bfloat162 h01, h23, l01, l23;
    h01.x = hh[0]; h01.y = hh[1]; h23.x = hh[2]; h23.y = hh[3];
    l01.x = ll[0]; l01.y = ll[1]; l23.x = ll[2]; l23.y = ll[3];
    *(__nv_bfloat162*)(h + i)     = h01;
    *(__nv_bfloat162*)(h + i + 2) = h23;
    *(__nv_bfloat162*)(l + i)     = l01;
    *(__nv_bfloat162*)(l + i + 2) = l23;
}

// ---------------------------------------------------------------------------
// HMMA bf16x3 GEMM (NT): C[M,N] = alpha * (A @ W^T + bias)
// 128x128 CTA tile, 8 warps (64x32 warp tiles), K chunks of 64,
// double-buffered cp.async, SW128-swizzled smem, ldmatrix fragments.
// smem stage layout: Ah @0, Al @16K, Bh @32K, Bl @48K (each 128x64 bf16).
//
// Swizzle invariant: per-k-step offset kOff (bits 5-6) is applied with XOR,
// because post-swizzle addresses may already carry bits 5-6 from row bits
// 7-9; ADD would carry into bit 7 and corrupt the row (round-3 NaN bug).
// Pre-swizzle bases have bits 5-6 clear, so swz(x + kOff) == swz(x) ^ kOff.
// ---------------------------------------------------------------------------
#define GK_STAGE 65536
#define GK_SMEM  (2 * GK_STAGE + 1024)

__global__ __launch_bounds__(256, 1)
void gemm_bf16x3(const __nv_bfloat16* __restrict__ Ah,
                 const __nv_bfloat16* __restrict__ Al,
                 const __nv_bfloat16* __restrict__ Bh,
                 const __nv_bfloat16* __restrict__ Bl,
                 const float* __restrict__ bias,
                 float* __restrict__ C,
                 int K, int N, float alpha)
{
    extern __shared__ char dsm[];
    const uint32_t sbase = (smem_u32(dsm) + 1023u) & ~1023u;

    const int tid = threadIdx.x;
    const int wid = tid >> 5;
    const int lane = tid & 31;
    const int wm = wid & 1;          // 0..1 -> M offset 64*wm
    const int wn = wid >> 1;         // 0..3 -> N offset 32*wn
    const int rowBase = blockIdx.y * 128;
    const int colBase = blockIdx.x * 128;

    const __nv_bfloat16* tAh = Ah + (size_t)rowBase * K;
    const __nv_bfloat16* tAl = Al + (size_t)rowBase * K;
    const __nv_bfloat16* tBh = Bh + (size_t)colBase * K;
    const __nv_bfloat16* tBl = Bl + (size_t)colBase * K;

#define LOAD_CHUNK(stg, k0) do {                                          \
    _Pragma("unroll")                                                     \
    for (int _i = 0; _i < 4; _i++) {                                      \
        int _s   = tid + _i * 256;                                        \
        int _row = _s >> 3;                                               \
        int _cb  = (_s & 7) * 16;                                         \
        uint32_t _sw = swz((uint32_t)(_row * 128 + _cb));                 \
        size_t _ge = (size_t)_row * K + (k0) + (_cb >> 1);                \
        cp_async16((stg) + _sw,         tAh + _ge);                       \
        cp_async16((stg) + 16384 + _sw, tAl + _ge);                       \
        cp_async16((stg) + 32768 + _sw, tBh + _ge);                       \
        cp_async16((stg) + 49152 + _sw, tBl + _ge);                       \
    }                                                                     \
    CP_COMMIT();                                                          \
} while (0)

    float acc[4][4][4];
#pragma unroll
    for (int mf = 0; mf < 4; mf++)
#pragma unroll
        for (int nf = 0; nf < 4; nf++)
#pragma unroll
            for (int e = 0; e < 4; e++) acc[mf][nf][e] = 0.f;

    // ldmatrix lane-address offsets (within a 128B/row tile), swizzled.
    // A x4: lanes 0-15 -> rows m..m+15 halfk0; lanes 16-31 -> same rows halfk1
    const uint32_t a_off = swz((uint32_t)((lane & 15) * 128 + ((lane >> 4) << 4)));
    // B x4: m0=n0-7 k0, m1=n0-7 k8, m2=n8-15 k0, m3=n8-15 k8
    const uint32_t b_off = swz((uint32_t)(
        (((lane >> 4) << 3) + (lane & 7)) * 128 + (((lane >> 3) & 1) << 4)));

    const int NCH = K >> 6;
    LOAD_CHUNK(sbase, 0);

    for (int k = 0; k < NCH; k++) {
        if (k + 1 < NCH) {
            LOAD_CHUNK(sbase + ((k + 1) & 1) * GK_STAGE, (k + 1) * 64);
            CP_WAIT(1);
        } else {
            CP_WAIT(0);
        }
        __syncthreads();

        const uint32_t st = sbase + (k & 1) * GK_STAGE;
        const uint32_t aBase = st + (uint32_t)(wm * 64 * 128) + a_off;
        const uint32_t bBase = st + 32768 + (uint32_t)(wn * 32 * 128) + b_off;

#pragma unroll
        for (int ks = 0; ks < 4; ks++) {
            const uint32_t kOff = (uint32_t)(ks * 32);   // bits 5-6 -> XOR!
            uint32_t bh[4][2], bl[4][2];
#pragma unroll
            for (int p = 0; p < 2; p++) {
                uint32_t addr = (bBase + (uint32_t)(p * 16 * 128)) ^ kOff;
                ldsm4(addr, bh[2 * p][0], bh[2 * p][1],
                            bh[2 * p + 1][0], bh[2 * p + 1][1]);
                ldsm4(addr + 16384, bl[2 * p][0], bl[2 * p][1],
                                    bl[2 * p + 1][0], bl[2 * p + 1][1]);
            }
#pragma unroll
            for (int mf = 0; mf < 4; mf++) {
                uint32_t addr = (aBase + (uint32_t)(mf * 16 * 128)) ^ kOff;
                uint32_t ah4[4], al4[4];
                ldsm4(addr, ah4[0], ah4[1], ah4[2], ah4[3]);
                ldsm4(addr + 16384, al4[0], al4[1], al4[2], al4[3]);
#pragma unroll
                for (int nf = 0; nf < 4; nf++) {
                    mma16816(acc[mf][nf], ah4, bh[nf]);
                    mma16816(acc[mf][nf], ah4, bl[nf]);
                    mma16816(acc[mf][nf], al4, bh[nf]);
                }
            }
        }
        __syncthreads();
    }

    // epilogue: D frag (m16n8): d0,d1 -> (row g, col 2t4); d2,d3 -> row g+8
    const int g  = lane >> 2;
    const int t4 = lane & 3;
#pragma unroll
    for (int mf = 0; mf < 4; mf++) {
#pragma unroll
        for (int nf = 0; nf < 4; nf++) {
            const int r0 = rowBase + wm * 64 + mf * 16 + g;
            const int c0 = colBase + wn * 32 + nf * 8 + t4 * 2;
            float b0 = 0.f, b1 = 0.f;
            if (bias) { b0 = bias[c0]; b1 = bias[c0 + 1]; }
            float2 o0, o1;
            o0.x = alpha * (acc[mf][nf][0] + b0);
            o0.y = alpha * (acc[mf][nf][1] + b1);
            o1.x = alpha * (acc[mf][nf][2] + b0);
            o1.y = alpha * (acc[mf][nf][3] + b1);
            *(float2*)(C + (size_t)r0 * N + c0)       = o0;
            *(float2*)(C + (size_t)(r0 + 8) * N + c0) = o1;
        }
    }
#undef LOAD_CHUNK
}

// ---------------------------------------------------------------------------
// Block-local attention (fp32, unchanged from round 1)
// ---------------------------------------------------------------------------
#define ATTN_SMEM_FLOATS (8192 + 8192 + 128 * 132)
#define ATTN_SMEM_BYTES  (ATTN_SMEM_FLOATS * 4)

__global__ __launch_bounds__(256)
void block_attn(const float* __restrict__ Q, const float* __restrict__ K,
                const float* __restrict__ V, float* __restrict__ O)
{
    extern __shared__ float sm[];
    float* q_s = sm;                 // [128][64]
    float* kT  = sm + 8192;          // [64][128]
    float* S   = sm + 16384;         // [128][132]
    float* v_s = sm;                 // aliases q_s

    __shared__ float redm[256];
    __shared__ float reds[256];

    const int tid = threadIdx.x;
    const int idx = blockIdx.x;
    const int h = idx & 15;
    const int n = (idx >> 4) & 31;
    const int b = idx >> 9;
    const size_t base = ((size_t)b * 4096 + (size_t)n * 128) * 1024 + (size_t)h * 64;

    for (int i = tid; i < 128 * 16; i += 256) {
        const int r  = i >> 4;
        const int c4 = (i & 15) << 2;
        const float4 qv = *(const float4*)(Q + base + (size_t)r * 1024 + c4);
        *(float4*)(q_s + r * 64 + c4) = qv;
        const float4 kv = *(const float4*)(K + base + (size_t)r * 1024 + c4);
        kT[(c4 + 0) * 128 + r] = kv.x;
        kT[(c4 + 1) * 128 + r] = kv.y;
        kT[(c4 + 2) * 128 + r] = kv.z;
        kT[(c4 + 3) * 128 + r] = kv.w;
    }
    __syncthreads();

    {
        const int tx = tid & 15, ty = tid >> 4;
        float acc[8][8];
#pragma unroll
        for (int i = 0; i < 8; i++)
#pragma unroll
            for (int j = 0; j < 8; j++) acc[i][j] = 0.f;

        for (int d = 0; d < 64; d++) {
            float ar[8], br[8];
#pragma unroll
            for (int i = 0; i < 8; i++) ar[i] = q_s[(ty * 8 + i) * 64 + d];
            *(float4*)(br)     = *(const float4*)(kT + d * 128 + tx * 8);
            *(float4*)(br + 4) = *(const float4*)(kT + d * 128 + tx * 8 + 4);
#pragma unroll
            for (int i = 0; i < 8; i++)
#pragma unroll
                for (int j = 0; j < 8; j++)
                    acc[i][j] = fmaf(ar[i], br[j], acc[i][j]);
        }
#pragma unroll
        for (int i = 0; i < 8; i++)
#pragma unroll
            for (int j = 0; j < 8; j++)
                S[(ty * 8 + i) * 132 + tx * 8 + j] = acc[i][j];
    }
    __syncthreads();

    for (int i = tid; i < 128 * 16; i += 256) {
        const int r  = i >> 4;
        const int c4 = (i & 15) << 2;
        *(float4*)(v_s + r * 64 + c4) =
            *(const float4*)(V + base + (size_t)r * 1024 + c4);
    }

    {
        const int r = tid >> 1;
        float* Srow = S + r * 132 + (tid & 1) * 64;
        float m = -CUDART_INF_F;
#pragma unroll 8
        for (int j = 0; j < 64; j++) m = fmaxf(m, Srow[j]);
        redm[tid] = m;
        __syncthreads();
        m = fmaxf(redm[r * 2], redm[r * 2 + 1]);
        float s = 0.f;
#pragma unroll 8
        for (int j = 0; j < 64; j++) {
            const float e = __expf(Srow[j] - m);
            Srow[j] = e;
            s += e;
        }
        reds[tid] = s;
        __syncthreads();
        const float inv = 1.f / (reds[r * 2] + reds[r * 2 + 1]);
#pragma unroll 8
        for (int j = 0; j < 64; j++) Srow[j] *= inv;
    }
    __syncthreads();

    {
        const int txb = tid & 7;
        const int tyb = tid >> 3;
        float acc[4][8];
#pragma unroll
        for (int i = 0; i < 4; i++)
#pragma unroll
            for (int j = 0; j < 8; j++) acc[i][j] = 0.f;

        for (int jj = 0; jj < 128; jj++) {
            float ar[4], br[8];
#pragma unroll
            for (int i = 0; i < 4; i++) ar[i] = S[(tyb * 4 + i) * 132 + jj];
            *(float4*)(br)     = *(const float4*)(v_s + jj * 64 + txb * 8);
            *(float4*)(br + 4) = *(const float4*)(v_s + jj * 64 + txb * 8 + 4);
#pragma unroll
            for (int i = 0; i < 4; i++)
#pragma unroll
                for (int j = 0; j < 8; j++)
                    acc[i][j] = fmaf(ar[i], br[j], acc[i][j]);
        }

#pragma unroll
        for (int i = 0; i < 4; i++) {
            float* Op = O + base + (size_t)(tyb * 4 + i) * 1024 + txb * 8;
            float4 o0, o1;
            o0.x = acc[i][0]; o0.y = acc[i][1]; o0.z = acc[i][2]; o0.w = acc[i][3];
            o1.x = acc[i][4]; o1.y = acc[i][5]; o1.z = acc[i][6]; o1.w = acc[i][7];
            *(float4*)(Op)     = o0;
            *(float4*)(Op + 4) = o1;
        }
    }
}

// ---------------------------------------------------------------------------
extern "C" void kernel_launch(void* const* d_in, const int* in_sizes, int n_in,
                              void* d_out, int out_size)
{
    const float* x  = (const float*)d_in[0];
    const float* Wq = (const float*)d_in[1];
    const float* bq = (const float*)d_in[2];
    const float* Wk = (const float*)d_in[3];
    const float* Wv = (const float*)d_in[4];
    const float* bv = (const float*)d_in[5];
    const float* Wo = (const float*)d_in[6];
    const float* bo = (const float*)d_in[7];
    float* out = (float*)d_out;

    float *q, *k, *v, *att;
    __nv_bfloat16 *xh, *xl, *ah, *al, *wh, *wl;
    cudaGetSymbolAddress((void**)&q,   g_q);
    cudaGetSymbolAddress((void**)&k,   g_k);
    cudaGetSymbolAddress((void**)&v,   g_v);
    cudaGetSymbolAddress((void**)&att, g_att);
    cudaGetSymbolAddress((void**)&xh,  g_xh);
    cudaGetSymbolAddress((void**)&xl,  g_xl);
    cudaGetSymbolAddress((void**)&ah,  g_ah);
    cudaGetSymbolAddress((void**)&al,  g_al);
    cudaGetSymbolAddress((void**)&wh,  g_wh);
    cudaGetSymbolAddress((void**)&wl,  g_wl);

    cudaFuncSetAttribute(block_attn,
                         cudaFuncAttributeMaxDynamicSharedMemorySize,
                         ATTN_SMEM_BYTES);
    cudaFuncSetAttribute(gemm_bf16x3,
                         cudaFuncAttributeMaxDynamicSharedMemorySize,
                         GK_SMEM);

    const int NX = M_ROWS * CDIM;
    const int NW = CDIM * CDIM;

    split_hi_lo<<<NX / 4 / 256, 256>>>(x, xh, xl, NX);
    split_hi_lo<<<NW / 4 / 256, 256>>>(Wq, wh + 0 * NW, wl + 0 * NW, NW);
    split_hi_lo<<<NW / 4 / 256, 256>>>(Wk, wh + 1 * NW, wl + 1 * NW, NW);
    split_hi_lo<<<NW / 4 / 256, 256>>>(Wv, wh + 2 * NW, wl + 2 * NW, NW);
    split_hi_lo<<<NW / 4 / 256, 256>>>(Wo, wh + 3 * NW, wl + 3 * NW, NW);

    const dim3 ggrid(CDIM / 128, M_ROWS / 128);   // (8, 128)

    gemm_bf16x3<<<ggrid, 256, GK_SMEM>>>(xh, xl, wh + 0 * NW, wl + 0 * NW,
                                         bq, q, CDIM, CDIM, QK_SCALE);
    gemm_bf16x3<<<ggrid, 256, GK_SMEM>>>(xh, xl, wh + 1 * NW, wl + 1 * NW,
                                         nullptr, k, CDIM, CDIM, QK_SCALE);
    gemm_bf16x3<<<ggrid, 256, GK_SMEM>>>(xh, xl, wh + 2 * NW, wl + 2 * NW,
                                         bv, v, CDIM, CDIM, 1.0f);

    block_attn<<<2048, 256, ATTN_SMEM_BYTES>>>(q, k, v, att);

    split_hi_lo<<<NX / 4 / 256, 256>>>(att, ah, al, NX);
    gemm_bf16x3<<<ggrid, 256, GK_SMEM>>>(ah, al, wh + 3 * NW, wl + 3 * NW,
                                         bo, out, CDIM, CDIM, 1.0f);
}

// round 5
// speedup vs baseline: 3.4093x; 1.2638x over previous
#include <cuda_runtime.h>
#include <cuda_bf16.h>
#include <math_constants.h>
#include <cstdint>

// ---------------------------------------------------------------------------
// MultiHeadAttention (block-local). Everything on HMMA (mma.sync bf16) with
// bf16x3 fp32 emulation. Projections write bf16 hi/lo pairs directly; the
// attention kernel consumes/produces hi/lo pairs (no fp32 scratch roundtrip).
// Shapes: B=4, T=4096, C=1024, H=16, HD=64, NBLOCKS=32, BSIZE=128
// ---------------------------------------------------------------------------

#define M_ROWS 16384
#define CDIM   1024
#define QK_SCALE 0.35355339059327376f   // 64^(-0.25)

// bf16 hi/lo scratch
__device__ __align__(256) __nv_bfloat16 g_xh[M_ROWS * CDIM];
__device__ __align__(256) __nv_bfloat16 g_xl[M_ROWS * CDIM];
__device__ __align__(256) __nv_bfloat16 g_qh[M_ROWS * CDIM];
__device__ __align__(256) __nv_bfloat16 g_ql[M_ROWS * CDIM];
__device__ __align__(256) __nv_bfloat16 g_kh[M_ROWS * CDIM];
__device__ __align__(256) __nv_bfloat16 g_kl[M_ROWS * CDIM];
__device__ __align__(256) __nv_bfloat16 g_vh[M_ROWS * CDIM];
__device__ __align__(256) __nv_bfloat16 g_vl[M_ROWS * CDIM];
__device__ __align__(256) __nv_bfloat16 g_ah[M_ROWS * CDIM];
__device__ __align__(256) __nv_bfloat16 g_al[M_ROWS * CDIM];
__device__ __align__(256) __nv_bfloat16 g_wh[4 * CDIM * CDIM];
__device__ __align__(256) __nv_bfloat16 g_wl[4 * CDIM * CDIM];

// ---------------------------------------------------------------------------
// helpers
// ---------------------------------------------------------------------------
__device__ __forceinline__ uint32_t smem_u32(const void* p) {
    uint32_t a;
    asm("{ .reg .u64 t; cvta.to.shared.u64 t, %1; cvt.u32.u64 %0, t; }"
        : "=r"(a) : "l"(p));
    return a;
}

__device__ __forceinline__ void cp_async16(uint32_t dst, const void* src) {
    asm volatile("cp.async.cg.shared.global [%0], [%1], 16;"
                 :: "r"(dst), "l"(src));
}
#define CP_COMMIT() asm volatile("cp.async.commit_group;" ::: "memory")
#define CP_WAIT(n)  asm volatile("cp.async.wait_group %0;" :: "n"(n) : "memory")

__device__ __forceinline__ void ldsm4(uint32_t addr, uint32_t& r0, uint32_t& r1,
                                      uint32_t& r2, uint32_t& r3) {
    asm volatile("ldmatrix.sync.aligned.m8n8.x4.shared.b16 {%0,%1,%2,%3}, [%4];"
                 : "=r"(r0), "=r"(r1), "=r"(r2), "=r"(r3) : "r"(addr));
}

__device__ __forceinline__ void mma16816(float* d, const uint32_t* a,
                                         const uint32_t* b) {
    asm volatile(
        "mma.sync.aligned.m16n8k16.row.col.f32.bf16.bf16.f32 "
        "{%0,%1,%2,%3}, {%4,%5,%6,%7}, {%8,%9}, {%0,%1,%2,%3};"
        : "+f"(d[0]), "+f"(d[1]), "+f"(d[2]), "+f"(d[3])
        : "r"(a[0]), "r"(a[1]), "r"(a[2]), "r"(a[3]), "r"(b[0]), "r"(b[1]));
}

__device__ __forceinline__ uint32_t swz(uint32_t off) {
    return off ^ ((off >> 3) & 0x70);
}

// split pair of fp32 into packed bf16x2 hi/lo (lo = residual)
__device__ __forceinline__ void split2(float a, float b,
                                       uint32_t& hi, uint32_t& lo) {
    __nv_bfloat16 ha = __float2bfloat16_rn(a);
    __nv_bfloat16 hb = __float2bfloat16_rn(b);
    __nv_bfloat16 la = __float2bfloat16_rn(a - __bfloat162float(ha));
    __nv_bfloat16 lb = __float2bfloat16_rn(b - __bfloat162float(hb));
    __nv_bfloat162 H; H.x = ha; H.y = hb;
    __nv_bfloat162 L; L.x = la; L.y = lb;
    hi = *(uint32_t*)&H;
    lo = *(uint32_t*)&L;
}

// ---------------------------------------------------------------------------
// fp32 -> bf16 hi/lo split (input x only)
// ---------------------------------------------------------------------------
__global__ void split_hi_lo(const float* __restrict__ x,
                            __nv_bfloat16* __restrict__ h,
                            __nv_bfloat16* __restrict__ l, int n)
{
    int i = (blockIdx.x * 256 + threadIdx.x) * 4;
    if (i >= n) return;
    float4 v = *(const float4*)(x + i);
    uint32_t h01, l01, h23, l23;
    split2(v.x, v.y, h01, l01);
    split2(v.z, v.w, h23, l23);
    *(uint32_t*)(h + i)     = h01;
    *(uint32_t*)(h + i + 2) = h23;
    *(uint32_t*)(l + i)     = l01;
    *(uint32_t*)(l + i + 2) = l23;
}

// ---------------------------------------------------------------------------
// HMMA bf16x3 GEMM (NT): out = alpha * (A @ W^T + bias)
// Output either fp32 (Cf) or split bf16 hi/lo (Ch/Cl) when Ch != nullptr.
// 128x128 CTA tile, 8 warps (64x32), K chunks of 64, double-buffered cp.async.
// Swizzle invariant: per-k-step offset (bits 5-6) applied with XOR (see R3).
// ---------------------------------------------------------------------------
#define GK_STAGE 65536
#define GK_SMEM  (2 * GK_STAGE + 1024)

__global__ __launch_bounds__(256, 1)
void gemm_bf16x3(const __nv_bfloat16* __restrict__ Ah,
                 const __nv_bfloat16* __restrict__ Al,
                 const __nv_bfloat16* __restrict__ Bh,
                 const __nv_bfloat16* __restrict__ Bl,
                 const float* __restrict__ bias,
                 float* __restrict__ Cf,
                 __nv_bfloat16* __restrict__ Ch,
                 __nv_bfloat16* __restrict__ Cl,
                 int K, int N, float alpha)
{
    extern __shared__ char dsm[];
    const uint32_t sbase = (smem_u32(dsm) + 1023u) & ~1023u;

    const int tid = threadIdx.x;
    const int wid = tid >> 5;
    const int lane = tid & 31;
    const int wm = wid & 1;
    const int wn = wid >> 1;
    const int rowBase = blockIdx.y * 128;
    const int colBase = blockIdx.x * 128;

    const __nv_bfloat16* tAh = Ah + (size_t)rowBase * K;
    const __nv_bfloat16* tAl = Al + (size_t)rowBase * K;
    const __nv_bfloat16* tBh = Bh + (size_t)colBase * K;
    const __nv_bfloat16* tBl = Bl + (size_t)colBase * K;

#define LOAD_CHUNK(stg, k0) do {                                          \
    _Pragma("unroll")                                                     \
    for (int _i = 0; _i < 4; _i++) {                                      \
        int _s   = tid + _i * 256;                                        \
        int _row = _s >> 3;                                               \
        int _cb  = (_s & 7) * 16;                                         \
        uint32_t _sw = swz((uint32_t)(_row * 128 + _cb));                 \
        size_t _ge = (size_t)_row * K + (k0) + (_cb >> 1);                \
        cp_async16((stg) + _sw,         tAh + _ge);                       \
        cp_async16((stg) + 16384 + _sw, tAl + _ge);                       \
        cp_async16((stg) + 32768 + _sw, tBh + _ge);                       \
        cp_async16((stg) + 49152 + _sw, tBl + _ge);                       \
    }                                                                     \
    CP_COMMIT();                                                          \
} while (0)

    float acc[4][4][4];
#pragma unroll
    for (int mf = 0; mf < 4; mf++)
#pragma unroll
        for (int nf = 0; nf < 4; nf++)
#pragma unroll
            for (int e = 0; e < 4; e++) acc[mf][nf][e] = 0.f;

    const uint32_t a_off = swz((uint32_t)((lane & 15) * 128 + ((lane >> 4) << 4)));
    const uint32_t b_off = swz((uint32_t)(
        (((lane >> 4) << 3) + (lane & 7)) * 128 + (((lane >> 3) & 1) << 4)));

    const int NCH = K >> 6;
    LOAD_CHUNK(sbase, 0);

    for (int k = 0; k < NCH; k++) {
        if (k + 1 < NCH) {
            LOAD_CHUNK(sbase + ((k + 1) & 1) * GK_STAGE, (k + 1) * 64);
            CP_WAIT(1);
        } else {
            CP_WAIT(0);
        }
        __syncthreads();

        const uint32_t st = sbase + (k & 1) * GK_STAGE;
        const uint32_t aBase = st + (uint32_t)(wm * 64 * 128) + a_off;
        const uint32_t bBase = st + 32768 + (uint32_t)(wn * 32 * 128) + b_off;

#pragma unroll
        for (int ks = 0; ks < 4; ks++) {
            const uint32_t kOff = (uint32_t)(ks * 32);   // bits 5-6 -> XOR
            uint32_t bh[4][2], bl[4][2];
#pragma unroll
            for (int p = 0; p < 2; p++) {
                uint32_t addr = (bBase + (uint32_t)(p * 16 * 128)) ^ kOff;
                ldsm4(addr, bh[2 * p][0], bh[2 * p][1],
                            bh[2 * p + 1][0], bh[2 * p + 1][1]);
                ldsm4(addr + 16384, bl[2 * p][0], bl[2 * p][1],
                                    bl[2 * p + 1][0], bl[2 * p + 1][1]);
            }
#pragma unroll
            for (int mf = 0; mf < 4; mf++) {
                uint32_t addr = (aBase + (uint32_t)(mf * 16 * 128)) ^ kOff;
                uint32_t ah4[4], al4[4];
                ldsm4(addr, ah4[0], ah4[1], ah4[2], ah4[3]);
                ldsm4(addr + 16384, al4[0], al4[1], al4[2], al4[3]);
#pragma unroll
                for (int nf = 0; nf < 4; nf++) {
                    mma16816(acc[mf][nf], ah4, bh[nf]);
                    mma16816(acc[mf][nf], ah4, bl[nf]);
                    mma16816(acc[mf][nf], al4, bh[nf]);
                }
            }
        }
        __syncthreads();
    }

    const int g  = lane >> 2;
    const int t4 = lane & 3;
#pragma unroll
    for (int mf = 0; mf < 4; mf++) {
#pragma unroll
        for (int nf = 0; nf < 4; nf++) {
            const int r0 = rowBase + wm * 64 + mf * 16 + g;
            const int c0 = colBase + wn * 32 + nf * 8 + t4 * 2;
            float b0 = 0.f, b1 = 0.f;
            if (bias) { b0 = bias[c0]; b1 = bias[c0 + 1]; }
            float v0 = alpha * (acc[mf][nf][0] + b0);
            float v1 = alpha * (acc[mf][nf][1] + b1);
            float v2 = alpha * (acc[mf][nf][2] + b0);
            float v3 = alpha * (acc[mf][nf][3] + b1);
            if (Ch) {
                uint32_t h0, l0, h1, l1;
                split2(v0, v1, h0, l0);
                split2(v2, v3, h1, l1);
                *(uint32_t*)(Ch + (size_t)r0 * N + c0)       = h0;
                *(uint32_t*)(Cl + (size_t)r0 * N + c0)       = l0;
                *(uint32_t*)(Ch + (size_t)(r0 + 8) * N + c0) = h1;
                *(uint32_t*)(Cl + (size_t)(r0 + 8) * N + c0) = l1;
            } else {
                float2 o0, o1;
                o0.x = v0; o0.y = v1;
                o1.x = v2; o1.y = v3;
                *(float2*)(Cf + (size_t)r0 * N + c0)       = o0;
                *(float2*)(Cf + (size_t)(r0 + 8) * N + c0) = o1;
            }
        }
    }
#undef LOAD_CHUNK
}

// ---------------------------------------------------------------------------
// Block-local attention on HMMA. One CTA per (b, block, head); 8 warps x 16
// rows. S = qh*kh + qh*kl + ql*kh (fp32 acc), softmax in regs, P split to
// bf16 hi/lo in regs, O = ph*vh + ph*vl + pl*vh. V is scatter-transposed
// into smem as two [64][64] tiles (128B rows) per hi/lo.
// smem: qh@0 ql@16K kh@32K kl@48K vT_h@64K vT_l@80K  (96 KB)
// ---------------------------------------------------------------------------
#define ATT_SMEM (96 * 1024 + 1024)

__global__ __launch_bounds__(256)
void block_attn_mma(const __nv_bfloat16* __restrict__ Qh,
                    const __nv_bfloat16* __restrict__ Ql,
                    const __nv_bfloat16* __restrict__ Kh,
                    const __nv_bfloat16* __restrict__ Kl,
                    const __nv_bfloat16* __restrict__ Vh,
                    const __nv_bfloat16* __restrict__ Vl,
                    __nv_bfloat16* __restrict__ Oh,
                    __nv_bfloat16* __restrict__ Ol)
{
    extern __shared__ char dsm[];
    const uint32_t sb0 = smem_u32(dsm);
    const uint32_t sbase = (sb0 + 1023u) & ~1023u;
    char* dsa = dsm + (sbase - sb0);

    const int tid = threadIdx.x;
    const int wid = tid >> 5;
    const int lane = tid & 31;

    const int idx = blockIdx.x;
    const int h = idx & 15, n = (idx >> 4) & 31, b = idx >> 9;
    const size_t base = ((size_t)b * 4096 + (size_t)n * 128) * 1024 + (size_t)h * 64;

    const uint32_t QH = 0, QL = 16384, KH = 32768, VH = 65536, VL = 81920;

    // q,k tiles (natural, SW128): cp.async
    for (int i = tid; i < 1024; i += 256) {
        int row = i >> 3;
        int cb = (i & 7) * 16;
        uint32_t sw = swz((uint32_t)(row * 128 + cb));
        size_t ge = base + (size_t)row * 1024 + (cb >> 1);
        cp_async16(sbase + QH + sw, Qh + ge);
        cp_async16(sbase + QL + sw, Ql + ge);
        cp_async16(sbase + KH + sw,         Kh + ge);
        cp_async16(sbase + KH + 16384 + sw, Kl + ge);
    }
    CP_COMMIT();

    // v scatter-transpose: vT[d][j] as two [64][64] tiles (jhalf)
    for (int i = tid; i < 1024; i += 256) {
        int j = i >> 3;
        int d0 = (i & 7) * 8;
        size_t ge = base + (size_t)j * 1024 + d0;
        uint4 hv = *(const uint4*)(Vh + ge);
        uint4 lv = *(const uint4*)(Vl + ge);
        const __nv_bfloat16* h8 = (const __nv_bfloat16*)&hv;
        const __nv_bfloat16* l8 = (const __nv_bfloat16*)&lv;
        uint32_t tb = (uint32_t)((j >> 6) * 8192);
        int jl = j & 63;
#pragma unroll
        for (int e = 0; e < 8; e++) {
            uint32_t off = swz((uint32_t)((d0 + e) * 128 + jl * 2));
            *(__nv_bfloat16*)(dsa + VH + tb + off) = h8[e];
            *(__nv_bfloat16*)(dsa + VL + tb + off) = l8[e];
        }
    }
    CP_WAIT(0);
    __syncthreads();

    const uint32_t a_off = swz((uint32_t)((lane & 15) * 128 + ((lane >> 4) << 4)));
    const uint32_t b_off = swz((uint32_t)(
        (((lane >> 4) << 3) + (lane & 7)) * 128 + (((lane >> 3) & 1) << 4)));

    // ---- S = q k^T : warp owns rows [wid*16, wid*16+16)
    float s[16][4];
#pragma unroll
    for (int nf = 0; nf < 16; nf++)
#pragma unroll
        for (int e = 0; e < 4; e++) s[nf][e] = 0.f;

    const uint32_t aQ = sbase + QH + (uint32_t)(wid * 16 * 128) + a_off;
#pragma unroll
    for (int ks = 0; ks < 4; ks++) {
        const uint32_t kOff = (uint32_t)(ks * 32);
        uint32_t qh4[4], ql4[4];
        ldsm4(aQ ^ kOff, qh4[0], qh4[1], qh4[2], qh4[3]);
        ldsm4((aQ ^ kOff) + 16384, ql4[0], ql4[1], ql4[2], ql4[3]);
#pragma unroll
        for (int p = 0; p < 8; p++) {
            uint32_t ab = (sbase + KH + (uint32_t)(p * 16 * 128) + b_off) ^ kOff;
            uint32_t bh[2][2], bl[2][2];
            ldsm4(ab, bh[0][0], bh[0][1], bh[1][0], bh[1][1]);
            ldsm4(ab + 16384, bl[0][0], bl[0][1], bl[1][0], bl[1][1]);
            mma16816(s[2 * p],     qh4, bh[0]);
            mma16816(s[2 * p],     qh4, bl[0]);
            mma16816(s[2 * p],     ql4, bh[0]);
            mma16816(s[2 * p + 1], qh4, bh[1]);
            mma16816(s[2 * p + 1], qh4, bl[1]);
            mma16816(s[2 * p + 1], ql4, bh[1]);
        }
    }

    // ---- softmax in registers (rows g and g+8; 4 lanes share a row)
    float m0 = -CUDART_INF_F, m1 = -CUDART_INF_F;
#pragma unroll
    for (int nf = 0; nf < 16; nf++) {
        m0 = fmaxf(m0, fmaxf(s[nf][0], s[nf][1]));
        m1 = fmaxf(m1, fmaxf(s[nf][2], s[nf][3]));
    }
    m0 = fmaxf(m0, __shfl_xor_sync(0xFFFFFFFFu, m0, 1));
    m0 = fmaxf(m0, __shfl_xor_sync(0xFFFFFFFFu, m0, 2));
    m1 = fmaxf(m1, __shfl_xor_sync(0xFFFFFFFFu, m1, 1));
    m1 = fmaxf(m1, __shfl_xor_sync(0xFFFFFFFFu, m1, 2));

    float sum0 = 0.f, sum1 = 0.f;
#pragma unroll
    for (int nf = 0; nf < 16; nf++) {
        s[nf][0] = __expf(s[nf][0] - m0); sum0 += s[nf][0];
        s[nf][1] = __expf(s[nf][1] - m0); sum0 += s[nf][1];
        s[nf][2] = __expf(s[nf][2] - m1); sum1 += s[nf][2];
        s[nf][3] = __expf(s[nf][3] - m1); sum1 += s[nf][3];
    }
    sum0 += __shfl_xor_sync(0xFFFFFFFFu, sum0, 1);
    sum0 += __shfl_xor_sync(0xFFFFFFFFu, sum0, 2);
    sum1 += __shfl_xor_sync(0xFFFFFFFFu, sum1, 1);
    sum1 += __shfl_xor_sync(0xFFFFFFFFu, sum1, 2);
    const float inv0 = 1.f / sum0;
    const float inv1 = 1.f / sum1;

    // P -> bf16 hi/lo fragments (D-layout == A-layout for the PV mma)
    uint32_t ph[16][2], pl[16][2];
#pragma unroll
    for (int nf = 0; nf < 16; nf++) {
        split2(s[nf][0] * inv0, s[nf][1] * inv0, ph[nf][0], pl[nf][0]);
        split2(s[nf][2] * inv1, s[nf][3] * inv1, ph[nf][1], pl[nf][1]);
    }

    // ---- O = P @ V (V^T tiles: [n=d rows][k=j cols])
    float o[8][4];
#pragma unroll
    for (int nf = 0; nf < 8; nf++)
#pragma unroll
        for (int e = 0; e < 4; e++) o[nf][e] = 0.f;

#pragma unroll
    for (int ks = 0; ks < 8; ks++) {
        uint32_t pa[4]  = { ph[2 * ks][0], ph[2 * ks][1],
                            ph[2 * ks + 1][0], ph[2 * ks + 1][1] };
        uint32_t pla[4] = { pl[2 * ks][0], pl[2 * ks][1],
                            pl[2 * ks + 1][0], pl[2 * ks + 1][1] };
        const uint32_t tb = sbase + VH + (uint32_t)((ks >> 2) * 8192);
        const uint32_t kOff = (uint32_t)((ks & 3) * 32);
#pragma unroll
        for (int p = 0; p < 4; p++) {
            uint32_t ab = (tb + (uint32_t)(p * 16 * 128) + b_off) ^ kOff;
            uint32_t bh[2][2], bl[2][2];
            ldsm4(ab, bh[0][0], bh[0][1], bh[1][0], bh[1][1]);
            ldsm4(ab + 16384, bl[0][0], bl[0][1], bl[1][0], bl[1][1]);
            mma16816(o[2 * p],     pa,  bh[0]);
            mma16816(o[2 * p],     pa,  bl[0]);
            mma16816(o[2 * p],     pla, bh[0]);
            mma16816(o[2 * p + 1], pa,  bh[1]);
            mma16816(o[2 * p + 1], pa,  bl[1]);
            mma16816(o[2 * p + 1], pla, bh[1]);
        }
    }

    // ---- epilogue: write att as bf16 hi/lo pairs
    const int g = lane >> 2, t4 = lane & 3;
#pragma unroll
    for (int nf = 0; nf < 8; nf++) {
        const int r0 = wid * 16 + g;
        const int c  = nf * 8 + t4 * 2;
        const size_t e0 = base + (size_t)r0 * 1024 + c;
        const size_t e1 = base + (size_t)(r0 + 8) * 1024 + c;
        uint32_t h0, l0, h1, l1;
        split2(o[nf][0], o[nf][1], h0, l0);
        split2(o[nf][2], o[nf][3], h1, l1);
        *(uint32_t*)(Oh + e0) = h0;
        *(uint32_t*)(Ol + e0) = l0;
        *(uint32_t*)(Oh + e1) = h1;
        *(uint32_t*)(Ol + e1) = l1;
    }
}

// ---------------------------------------------------------------------------
extern "C" void kernel_launch(void* const* d_in, const int* in_sizes, int n_in,
                              void* d_out, int out_size)
{
    const float* x  = (const float*)d_in[0];
    const float* Wq = (const float*)d_in[1];
    const float* bq = (const float*)d_in[2];
    const float* Wk = (const float*)d_in[3];
    const float* Wv = (const float*)d_in[4];
    const float* bv = (const float*)d_in[5];
    const float* Wo = (const float*)d_in[6];
    const float* bo = (const float*)d_in[7];
    float* out = (float*)d_out;

    __nv_bfloat16 *xh, *xl, *qh, *ql, *kh, *kl, *vh, *vl, *ah, *al, *wh, *wl;
    cudaGetSymbolAddress((void**)&xh, g_xh);
    cudaGetSymbolAddress((void**)&xl, g_xl);
    cudaGetSymbolAddress((void**)&qh, g_qh);
    cudaGetSymbolAddress((void**)&ql, g_ql);
    cudaGetSymbolAddress((void**)&kh, g_kh);
    cudaGetSymbolAddress((void**)&kl, g_kl);
    cudaGetSymbolAddress((void**)&vh, g_vh);
    cudaGetSymbolAddress((void**)&vl, g_vl);
    cudaGetSymbolAddress((void**)&ah, g_ah);
    cudaGetSymbolAddress((void**)&al, g_al);
    cudaGetSymbolAddress((void**)&wh, g_wh);
    cudaGetSymbolAddress((void**)&wl, g_wl);

    cudaFuncSetAttribute(gemm_bf16x3,
                         cudaFuncAttributeMaxDynamicSharedMemorySize, GK_SMEM);
    cudaFuncSetAttribute(block_attn_mma,
                         cudaFuncAttributeMaxDynamicSharedMemorySize, ATT_SMEM);

    const int NX = M_ROWS * CDIM;
    const int NW = CDIM * CDIM;

    split_hi_lo<<<NX / 4 / 256, 256>>>(x, xh, xl, NX);
    split_hi_lo<<<NW / 4 / 256, 256>>>(Wq, wh + 0 * NW, wl + 0 * NW, NW);
    split_hi_lo<<<NW / 4 / 256, 256>>>(Wk, wh + 1 * NW, wl + 1 * NW, NW);
    split_hi_lo<<<NW / 4 / 256, 256>>>(Wv, wh + 2 * NW, wl + 2 * NW, NW);
    split_hi_lo<<<NW / 4 / 256, 256>>>(Wo, wh + 3 * NW, wl + 3 * NW, NW);

    const dim3 ggrid(CDIM / 128, M_ROWS / 128);   // (8, 128)

    // projections -> split bf16 outputs (scale baked into q and k)
    gemm_bf16x3<<<ggrid, 256, GK_SMEM>>>(xh, xl, wh + 0 * NW, wl + 0 * NW,
                                         bq, nullptr, qh, ql, CDIM, CDIM, QK_SCALE);
    gemm_bf16x3<<<ggrid, 256, GK_SMEM>>>(xh, xl, wh + 1 * NW, wl + 1 * NW,
                                         nullptr, nullptr, kh, kl, CDIM, CDIM, QK_SCALE);
    gemm_bf16x3<<<ggrid, 256, GK_SMEM>>>(xh, xl, wh + 2 * NW, wl + 2 * NW,
                                         bv, nullptr, vh, vl, CDIM, CDIM, 1.0f);

    // block-local attention on HMMA -> split bf16 att
    block_attn_mma<<<2048, 256, ATT_SMEM>>>(qh, ql, kh, kl, vh, vl, ah, al);

    // output projection -> fp32 out
    gemm_bf16x3<<<ggrid, 256, GK_SMEM>>>(ah, al, wh + 3 * NW, wl + 3 * NW,
                                         bo, out, nullptr, nullptr, CDIM, CDIM, 1.0f);
}

// round 6
// speedup vs baseline: 4.9519x; 1.4525x over previous
#include <cuda_runtime.h>
#include <cuda_fp16.h>
#include <math_constants.h>
#include <cstdint>

// ---------------------------------------------------------------------------
// MultiHeadAttention (block-local). All matmuls on HMMA (mma.sync m16n8k16
// fp16, fp32 accumulate) using the fp16x2 scheme: A = Ah + Al (exact split),
// B = single fp16 rounding. Error ~2^-12 incoherent => rel_err ~2-4e-4.
// Shapes: B=4, T=4096, C=1024, H=16, HD=64, NBLOCKS=32, BSIZE=128
// ---------------------------------------------------------------------------

#define M_ROWS 16384
#define CDIM   1024
#define QK_SCALE 0.35355339059327376f   // 64^(-0.25)

// fp16 scratch
__device__ __align__(256) __half g_xh[M_ROWS * CDIM];
__device__ __align__(256) __half g_xl[M_ROWS * CDIM];
__device__ __align__(256) __half g_qh[M_ROWS * CDIM];
__device__ __align__(256) __half g_ql[M_ROWS * CDIM];
__device__ __align__(256) __half g_ks[M_ROWS * CDIM];
__device__ __align__(256) __half g_vs[M_ROWS * CDIM];
__device__ __align__(256) __half g_ah[M_ROWS * CDIM];
__device__ __align__(256) __half g_al[M_ROWS * CDIM];
__device__ __align__(256) __half g_w[4 * CDIM * CDIM];

// ---------------------------------------------------------------------------
// helpers
// ---------------------------------------------------------------------------
__device__ __forceinline__ uint32_t smem_u32(const void* p) {
    uint32_t a;
    asm("{ .reg .u64 t; cvta.to.shared.u64 t, %1; cvt.u32.u64 %0, t; }"
        : "=r"(a) : "l"(p));
    return a;
}

__device__ __forceinline__ void cp_async16(uint32_t dst, const void* src) {
    asm volatile("cp.async.cg.shared.global [%0], [%1], 16;"
                 :: "r"(dst), "l"(src));
}
#define CP_COMMIT() asm volatile("cp.async.commit_group;" ::: "memory")
#define CP_WAIT(n)  asm volatile("cp.async.wait_group %0;" :: "n"(n) : "memory")

__device__ __forceinline__ void ldsm4(uint32_t addr, uint32_t& r0, uint32_t& r1,
                                      uint32_t& r2, uint32_t& r3) {
    asm volatile("ldmatrix.sync.aligned.m8n8.x4.shared.b16 {%0,%1,%2,%3}, [%4];"
                 : "=r"(r0), "=r"(r1), "=r"(r2), "=r"(r3) : "r"(addr));
}

__device__ __forceinline__ void mma16816(float* d, const uint32_t* a,
                                         const uint32_t* b) {
    asm volatile(
        "mma.sync.aligned.m16n8k16.row.col.f32.f16.f16.f32 "
        "{%0,%1,%2,%3}, {%4,%5,%6,%7}, {%8,%9}, {%0,%1,%2,%3};"
        : "+f"(d[0]), "+f"(d[1]), "+f"(d[2]), "+f"(d[3])
        : "r"(a[0]), "r"(a[1]), "r"(a[2]), "r"(a[3]), "r"(b[0]), "r"(b[1]));
}

__device__ __forceinline__ uint32_t swz(uint32_t off) {
    return off ^ ((off >> 3) & 0x70);
}

// split pair of fp32 into packed fp16x2 hi/lo (lo = residual)
__device__ __forceinline__ void split2h(float a, float b,
                                        uint32_t& hi, uint32_t& lo) {
    __half ha = __float2half_rn(a);
    __half hb = __float2half_rn(b);
    __half la = __float2half_rn(a - __half2float(ha));
    __half lb = __float2half_rn(b - __half2float(hb));
    __half2 H = __halves2half2(ha, hb);
    __half2 L = __halves2half2(la, lb);
    hi = *(uint32_t*)&H;
    lo = *(uint32_t*)&L;
}

__device__ __forceinline__ uint32_t pack2h(float a, float b) {
    __half2 H = __floats2half2_rn(a, b);
    return *(uint32_t*)&H;
}

// ---------------------------------------------------------------------------
// conversion kernels
// ---------------------------------------------------------------------------
__global__ void split_fp16x2(const float* __restrict__ x,
                             __half* __restrict__ h,
                             __half* __restrict__ l, int n)
{
    int i = (blockIdx.x * 256 + threadIdx.x) * 4;
    if (i >= n) return;
    float4 v = *(const float4*)(x + i);
    uint32_t h01, l01, h23, l23;
    split2h(v.x, v.y, h01, l01);
    split2h(v.z, v.w, h23, l23);
    *(uint32_t*)(h + i)     = h01;
    *(uint32_t*)(h + i + 2) = h23;
    *(uint32_t*)(l + i)     = l01;
    *(uint32_t*)(l + i + 2) = l23;
}

__global__ void to_fp16(const float* __restrict__ x,
                        __half* __restrict__ h, int n)
{
    int i = (blockIdx.x * 256 + threadIdx.x) * 4;
    if (i >= n) return;
    float4 v = *(const float4*)(x + i);
    *(uint32_t*)(h + i)     = pack2h(v.x, v.y);
    *(uint32_t*)(h + i + 2) = pack2h(v.z, v.w);
}

// ---------------------------------------------------------------------------
// HMMA fp16x2 GEMM (NT): out = alpha * ((Ah+Al) @ B^T + bias)
// Output modes: Cf (fp32) | Ch+Cl (fp16 split) | Ch only (fp16 single).
// 128x128 CTA tile, 8 warps (64x32), K chunks of 64, 3-stage cp.async ring.
// smem stage: Ah@0, Al@16K, B@32K (48 KB/stage).
// Swizzle invariant: per-k-step offset (bits 5-6) applied with XOR (see R3).
// ---------------------------------------------------------------------------
#define GK_STAGE 49152
#define GK_SMEM  (3 * GK_STAGE + 1024)

__global__ __launch_bounds__(256, 1)
void gemm_fp16x2(const __half* __restrict__ Ah,
                 const __half* __restrict__ Al,
                 const __half* __restrict__ Bs,
                 const float* __restrict__ bias,
                 float* __restrict__ Cf,
                 __half* __restrict__ Ch,
                 __half* __restrict__ Cl,
                 int K, int N, float alpha)
{
    extern __shared__ char dsm[];
    const uint32_t sbase = (smem_u32(dsm) + 1023u) & ~1023u;

    const int tid = threadIdx.x;
    const int wid = tid >> 5;
    const int lane = tid & 31;
    const int wm = wid & 1;
    const int wn = wid >> 1;
    const int rowBase = blockIdx.y * 128;
    const int colBase = blockIdx.x * 128;

    const __half* tAh = Ah + (size_t)rowBase * K;
    const __half* tAl = Al + (size_t)rowBase * K;
    const __half* tBs = Bs + (size_t)colBase * K;

#define LOAD_CHUNK(si, k0) do {                                           \
    uint32_t _stg = sbase + (uint32_t)(si) * GK_STAGE;                    \
    _Pragma("unroll")                                                     \
    for (int _i = 0; _i < 4; _i++) {                                      \
        int _s   = tid + _i * 256;                                        \
        int _row = _s >> 3;                                               \
        int _cb  = (_s & 7) * 16;                                         \
        uint32_t _sw = swz((uint32_t)(_row * 128 + _cb));                 \
        size_t _ge = (size_t)_row * K + (k0) + (_cb >> 1);                \
        cp_async16(_stg + _sw,         tAh + _ge);                        \
        cp_async16(_stg + 16384 + _sw, tAl + _ge);                        \
        cp_async16(_stg + 32768 + _sw, tBs + _ge);                        \
    }                                                                     \
    CP_COMMIT();                                                          \
} while (0)

    float acc[4][4][4];
#pragma unroll
    for (int mf = 0; mf < 4; mf++)
#pragma unroll
        for (int nf = 0; nf < 4; nf++)
#pragma unroll
            for (int e = 0; e < 4; e++) acc[mf][nf][e] = 0.f;

    const uint32_t a_off = swz((uint32_t)((lane & 15) * 128 + ((lane >> 4) << 4)));
    const uint32_t b_off = swz((uint32_t)(
        (((lane >> 4) << 3) + (lane & 7)) * 128 + (((lane >> 3) & 1) << 4)));

    const int NCH = K >> 6;      // 16
    LOAD_CHUNK(0, 0);
    LOAD_CHUNK(1, 64);

    for (int k = 0; k < NCH; k++) {
        if (k + 1 < NCH) CP_WAIT(1); else CP_WAIT(0);
        __syncthreads();
        if (k + 2 < NCH) LOAD_CHUNK((k + 2) % 3, (k + 2) * 64);

        const uint32_t st = sbase + (uint32_t)(k % 3) * GK_STAGE;
        const uint32_t aBase = st + (uint32_t)(wm * 64 * 128) + a_off;
        const uint32_t bBase = st + 32768 + (uint32_t)(wn * 32 * 128) + b_off;

#pragma unroll
        for (int ks = 0; ks < 4; ks++) {
            const uint32_t kOff = (uint32_t)(ks * 32);   // bits 5-6 -> XOR
            uint32_t bf[4][2];
#pragma unroll
            for (int p = 0; p < 2; p++) {
                uint32_t addr = (bBase + (uint32_t)(p * 16 * 128)) ^ kOff;
                ldsm4(addr, bf[2 * p][0], bf[2 * p][1],
                            bf[2 * p + 1][0], bf[2 * p + 1][1]);
            }
#pragma unroll
            for (int mf = 0; mf < 4; mf++) {
                uint32_t addr = (aBase + (uint32_t)(mf * 16 * 128)) ^ kOff;
                uint32_t ah4[4], al4[4];
                ldsm4(addr, ah4[0], ah4[1], ah4[2], ah4[3]);
                ldsm4(addr + 16384, al4[0], al4[1], al4[2], al4[3]);
#pragma unroll
                for (int nf = 0; nf < 4; nf++) {
                    mma16816(acc[mf][nf], ah4, bf[nf]);
                    mma16816(acc[mf][nf], al4, bf[nf]);
                }
            }
        }
    }

    const int g  = lane >> 2;
    const int t4 = lane & 3;
#pragma unroll
    for (int mf = 0; mf < 4; mf++) {
#pragma unroll
        for (int nf = 0; nf < 4; nf++) {
            const int r0 = rowBase + wm * 64 + mf * 16 + g;
            const int c0 = colBase + wn * 32 + nf * 8 + t4 * 2;
            float b0 = 0.f, b1 = 0.f;
            if (bias) { b0 = bias[c0]; b1 = bias[c0 + 1]; }
            float v0 = alpha * (acc[mf][nf][0] + b0);
            float v1 = alpha * (acc[mf][nf][1] + b1);
            float v2 = alpha * (acc[mf][nf][2] + b0);
            float v3 = alpha * (acc[mf][nf][3] + b1);
            if (Cf) {
                float2 o0, o1;
                o0.x = v0; o0.y = v1;
                o1.x = v2; o1.y = v3;
                *(float2*)(Cf + (size_t)r0 * N + c0)       = o0;
                *(float2*)(Cf + (size_t)(r0 + 8) * N + c0) = o1;
            } else if (Cl) {
                uint32_t h0, l0, h1, l1;
                split2h(v0, v1, h0, l0);
                split2h(v2, v3, h1, l1);
                *(uint32_t*)(Ch + (size_t)r0 * N + c0)       = h0;
                *(uint32_t*)(Cl + (size_t)r0 * N + c0)       = l0;
                *(uint32_t*)(Ch + (size_t)(r0 + 8) * N + c0) = h1;
                *(uint32_t*)(Cl + (size_t)(r0 + 8) * N + c0) = l1;
            } else {
                *(uint32_t*)(Ch + (size_t)r0 * N + c0)       = pack2h(v0, v1);
                *(uint32_t*)(Ch + (size_t)(r0 + 8) * N + c0) = pack2h(v2, v3);
            }
        }
    }
#undef LOAD_CHUNK
}

// ---------------------------------------------------------------------------
// Block-local attention on HMMA, fp16x2 scheme.
// S = (qh+ql)*k (k single fp16), softmax in regs, P split in regs,
// O = (ph+pl)*v (v single fp16, scatter-transposed in smem).
// smem: qh@0 ql@16K k@32K vT@48K (two [64][64] tiles) = 64 KB.
// ---------------------------------------------------------------------------
#define ATT_SMEM (64 * 1024 + 1024)

__global__ __launch_bounds__(256)
void block_attn_mma(const __half* __restrict__ Qh,
                    const __half* __restrict__ Ql,
                    const __half* __restrict__ Ks,
                    const __half* __restrict__ Vs,
                    __half* __restrict__ Oh,
                    __half* __restrict__ Ol)
{
    extern __shared__ char dsm[];
    const uint32_t sb0 = smem_u32(dsm);
    const uint32_t sbase = (sb0 + 1023u) & ~1023u;
    char* dsa = dsm + (sbase - sb0);

    const int tid = threadIdx.x;
    const int wid = tid >> 5;
    const int lane = tid & 31;

    const int idx = blockIdx.x;
    const int h = idx & 15, n = (idx >> 4) & 31, b = idx >> 9;
    const size_t base = ((size_t)b * 4096 + (size_t)n * 128) * 1024 + (size_t)h * 64;

    const uint32_t QH = 0, QL = 16384, KS = 32768, VT = 49152;

    // q hi/lo + k tiles (natural, SW128) via cp.async
    for (int i = tid; i < 1024; i += 256) {
        int row = i >> 3;
        int cb = (i & 7) * 16;
        uint32_t sw = swz((uint32_t)(row * 128 + cb));
        size_t ge = base + (size_t)row * 1024 + (cb >> 1);
        cp_async16(sbase + QH + sw, Qh + ge);
        cp_async16(sbase + QL + sw, Ql + ge);
        cp_async16(sbase + KS + sw, Ks + ge);
    }
    CP_COMMIT();

    // v scatter-transpose: vT[d][j], two [64][64] tiles by j-half
    for (int i = tid; i < 1024; i += 256) {
        int j = i >> 3;
        int d0 = (i & 7) * 8;
        size_t ge = base + (size_t)j * 1024 + d0;
        uint4 hv = *(const uint4*)(Vs + ge);
        const __half* h8 = (const __half*)&hv;
        uint32_t tb = (uint32_t)((j >> 6) * 8192);
        int jl = j & 63;
#pragma unroll
        for (int e = 0; e < 8; e++) {
            uint32_t off = swz((uint32_t)((d0 + e) * 128 + jl * 2));
            *(__half*)(dsa + VT + tb + off) = h8[e];
        }
    }
    CP_WAIT(0);
    __syncthreads();

    const uint32_t a_off = swz((uint32_t)((lane & 15) * 128 + ((lane >> 4) << 4)));
    const uint32_t b_off = swz((uint32_t)(
        (((lane >> 4) << 3) + (lane & 7)) * 128 + (((lane >> 3) & 1) << 4)));

    // ---- S = q k^T : warp owns rows [wid*16, wid*16+16)
    float s[16][4];
#pragma unroll
    for (int nf = 0; nf < 16; nf++)
#pragma unroll
        for (int e = 0; e < 4; e++) s[nf][e] = 0.f;

    const uint32_t aQ = sbase + QH + (uint32_t)(wid * 16 * 128) + a_off;
#pragma unroll
    for (int ks = 0; ks < 4; ks++) {
        const uint32_t kOff = (uint32_t)(ks * 32);
        uint32_t qh4[4], ql4[4];
        ldsm4(aQ ^ kOff, qh4[0], qh4[1], qh4[2], qh4[3]);
        ldsm4((aQ ^ kOff) + 16384, ql4[0], ql4[1], ql4[2], ql4[3]);
#pragma unroll
        for (int p = 0; p < 8; p++) {
            uint32_t ab = (sbase + KS + (uint32_t)(p * 16 * 128) + b_off) ^ kOff;
            uint32_t bk[2][2];
            ldsm4(ab, bk[0][0], bk[0][1], bk[1][0], bk[1][1]);
            mma16816(s[2 * p],     qh4, bk[0]);
            mma16816(s[2 * p],     ql4, bk[0]);
            mma16816(s[2 * p + 1], qh4, bk[1]);
            mma16816(s[2 * p + 1], ql4, bk[1]);
        }
    }

    // ---- softmax in registers (rows g and g+8; 4 lanes share a row)
    float m0 = -CUDART_INF_F, m1 = -CUDART_INF_F;
#pragma unroll
    for (int nf = 0; nf < 16; nf++) {
        m0 = fmaxf(m0, fmaxf(s[nf][0], s[nf][1]));
        m1 = fmaxf(m1, fmaxf(s[nf][2], s[nf][3]));
    }
    m0 = fmaxf(m0, __shfl_xor_sync(0xFFFFFFFFu, m0, 1));
    m0 = fmaxf(m0, __shfl_xor_sync(0xFFFFFFFFu, m0, 2));
    m1 = fmaxf(m1, __shfl_xor_sync(0xFFFFFFFFu, m1, 1));
    m1 = fmaxf(m1, __shfl_xor_sync(0xFFFFFFFFu, m1, 2));

    float sum0 = 0.f, sum1 = 0.f;
#pragma unroll
    for (int nf = 0; nf < 16; nf++) {
        s[nf][0] = __expf(s[nf][0] - m0); sum0 += s[nf][0];
        s[nf][1] = __expf(s[nf][1] - m0); sum0 += s[nf][1];
        s[nf][2] = __expf(s[nf][2] - m1); sum1 += s[nf][2];
        s[nf][3] = __expf(s[nf][3] - m1); sum1 += s[nf][3];
    }
    sum0 += __shfl_xor_sync(0xFFFFFFFFu, sum0, 1);
    sum0 += __shfl_xor_sync(0xFFFFFFFFu, sum0, 2);
    sum1 += __shfl_xor_sync(0xFFFFFFFFu, sum1, 1);
    sum1 += __shfl_xor_sync(0xFFFFFFFFu, sum1, 2);
    const float inv0 = 1.f / sum0;
    const float inv1 = 1.f / sum1;

    // P -> fp16 hi/lo fragments (D-layout == A-layout for the PV mma)
    uint32_t ph[16][2], pl[16][2];
#pragma unroll
    for (int nf = 0; nf < 16; nf++) {
        split2h(s[nf][0] * inv0, s[nf][1] * inv0, ph[nf][0], pl[nf][0]);
        split2h(s[nf][2] * inv1, s[nf][3] * inv1, ph[nf][1], pl[nf][1]);
    }

    // ---- O = P @ V (V^T tiles: [n=d rows][k=j cols])
    float o[8][4];
#pragma unroll
    for (int nf = 0; nf < 8; nf++)
#pragma unroll
        for (int e = 0; e < 4; e++) o[nf][e] = 0.f;

#pragma unroll
    for (int ks = 0; ks < 8; ks++) {
        uint32_t pa[4]  = { ph[2 * ks][0], ph[2 * ks][1],
                            ph[2 * ks + 1][0], ph[2 * ks + 1][1] };
        uint32_t pla[4] = { pl[2 * ks][0], pl[2 * ks][1],
                            pl[2 * ks + 1][0], pl[2 * ks + 1][1] };
        const uint32_t tb = sbase + VT + (uint32_t)((ks >> 2) * 8192);
        const uint32_t kOff = (uint32_t)((ks & 3) * 32);
#pragma unroll
        for (int p = 0; p < 4; p++) {
            uint32_t ab = (tb + (uint32_t)(p * 16 * 128) + b_off) ^ kOff;
            uint32_t bv[2][2];
            ldsm4(ab, bv[0][0], bv[0][1], bv[1][0], bv[1][1]);
            mma16816(o[2 * p],     pa,  bv[0]);
            mma16816(o[2 * p],     pla, bv[0]);
            mma16816(o[2 * p + 1], pa,  bv[1]);
            mma16816(o[2 * p + 1], pla, bv[1]);
        }
    }

    // ---- epilogue: write att as fp16 hi/lo pairs
    const int g = lane >> 2, t4 = lane & 3;
#pragma unroll
    for (int nf = 0; nf < 8; nf++) {
        const int r0 = wid * 16 + g;
        const int c  = nf * 8 + t4 * 2;
        const size_t e0 = base + (size_t)r0 * 1024 + c;
        const size_t e1 = base + (size_t)(r0 + 8) * 1024 + c;
        uint32_t h0, l0, h1, l1;
        split2h(o[nf][0], o[nf][1], h0, l0);
        split2h(o[nf][2], o[nf][3], h1, l1);
        *(uint32_t*)(Oh + e0) = h0;
        *(uint32_t*)(Ol + e0) = l0;
        *(uint32_t*)(Oh + e1) = h1;
        *(uint32_t*)(Ol + e1) = l1;
    }
}

// ---------------------------------------------------------------------------
extern "C" void kernel_launch(void* const* d_in, const int* in_sizes, int n_in,
                              void* d_out, int out_size)
{
    const float* x  = (const float*)d_in[0];
    const float* Wq = (const float*)d_in[1];
    const float* bq = (const float*)d_in[2];
    const float* Wk = (const float*)d_in[3];
    const float* Wv = (const float*)d_in[4];
    const float* bv = (const float*)d_in[5];
    const float* Wo = (const float*)d_in[6];
    const float* bo = (const float*)d_in[7];
    float* out = (float*)d_out;

    __half *xh, *xl, *qh, *ql, *ks, *vs, *ah, *al, *w;
    cudaGetSymbolAddress((void**)&xh, g_xh);
    cudaGetSymbolAddress((void**)&xl, g_xl);
    cudaGetSymbolAddress((void**)&qh, g_qh);
    cudaGetSymbolAddress((void**)&ql, g_ql);
    cudaGetSymbolAddress((void**)&ks, g_ks);
    cudaGetSymbolAddress((void**)&vs, g_vs);
    cudaGetSymbolAddress((void**)&ah, g_ah);
    cudaGetSymbolAddress((void**)&al, g_al);
    cudaGetSymbolAddress((void**)&w,  g_w);

    cudaFuncSetAttribute(gemm_fp16x2,
                         cudaFuncAttributeMaxDynamicSharedMemorySize, GK_SMEM);
    cudaFuncSetAttribute(block_attn_mma,
                         cudaFuncAttributeMaxDynamicSharedMemorySize, ATT_SMEM);

    const int NX = M_ROWS * CDIM;
    const int NW = CDIM * CDIM;

    split_fp16x2<<<NX / 4 / 256, 256>>>(x, xh, xl, NX);
    to_fp16<<<NW / 4 / 256, 256>>>(Wq, w + 0 * NW, NW);
    to_fp16<<<NW / 4 / 256, 256>>>(Wk, w + 1 * NW, NW);
    to_fp16<<<NW / 4 / 256, 256>>>(Wv, w + 2 * NW, NW);
    to_fp16<<<NW / 4 / 256, 256>>>(Wo, w + 3 * NW, NW);

    const dim3 ggrid(CDIM / 128, M_ROWS / 128);   // (8, 128)

    // projections (scale baked into q and k)
    gemm_fp16x2<<<ggrid, 256, GK_SMEM>>>(xh, xl, w + 0 * NW, bq,
                                         nullptr, qh, ql, CDIM, CDIM, QK_SCALE);
    gemm_fp16x2<<<ggrid, 256, GK_SMEM>>>(xh, xl, w + 1 * NW, nullptr,
                                         nullptr, ks, nullptr, CDIM, CDIM, QK_SCALE);
    gemm_fp16x2<<<ggrid, 256, GK_SMEM>>>(xh, xl, w + 2 * NW, bv,
                                         nullptr, vs, nullptr, CDIM, CDIM, 1.0f);

    // block-local attention -> split fp16 att
    block_attn_mma<<<2048, 256, ATT_SMEM>>>(qh, ql, ks, vs, ah, al);

    // output projection -> fp32 out
    gemm_fp16x2<<<ggrid, 256, GK_SMEM>>>(ah, al, w + 3 * NW, bo,
                                         out, nullptr, nullptr, CDIM, CDIM, 1.0f);
}

// round 8
// speedup vs baseline: 6.8367x; 1.3806x over previous
#include <cuda_runtime.h>
#include <cuda_fp16.h>
#include <math_constants.h>
#include <cstdint>

// ---------------------------------------------------------------------------
// MultiHeadAttention (block-local). All matmuls on HMMA (mma.sync m16n8k16
// fp16, fp32 acc). fp16x2 scheme (A=Ah+Al, B single fp16) for q/out GEMMs and
// attention; fp16x1 for k/v projections (their outputs are fp16-rounded
// anyway, so the Al term is below the noise floor).
// Shapes: B=4, T=4096, C=1024, H=16, HD=64, NBLOCKS=32, BSIZE=128
// ---------------------------------------------------------------------------

#define M_ROWS 16384
#define CDIM   1024
#define QK_SCALE 0.35355339059327376f   // 64^(-0.25)

__device__ __align__(256) __half g_xh[M_ROWS * CDIM];
__device__ __align__(256) __half g_xl[M_ROWS * CDIM];
__device__ __align__(256) __half g_qh[M_ROWS * CDIM];
__device__ __align__(256) __half g_ql[M_ROWS * CDIM];
__device__ __align__(256) __half g_ks[M_ROWS * CDIM];
__device__ __align__(256) __half g_vs[M_ROWS * CDIM];
__device__ __align__(256) __half g_ah[M_ROWS * CDIM];
__device__ __align__(256) __half g_al[M_ROWS * CDIM];
__device__ __align__(256) __half g_w[4 * CDIM * CDIM];

// ---------------------------------------------------------------------------
// helpers
// ---------------------------------------------------------------------------
__device__ __forceinline__ uint32_t smem_u32(const void* p) {
    uint32_t a;
    asm("{ .reg .u64 t; cvta.to.shared.u64 t, %1; cvt.u32.u64 %0, t; }"
        : "=r"(a) : "l"(p));
    return a;
}

__device__ __forceinline__ void cp_async16(uint32_t dst, const void* src) {
    asm volatile("cp.async.cg.shared.global [%0], [%1], 16;"
                 :: "r"(dst), "l"(src));
}
#define CP_COMMIT() asm volatile("cp.async.commit_group;" ::: "memory")
#define CP_WAIT(n)  asm volatile("cp.async.wait_group %0;" :: "n"(n) : "memory")

__device__ __forceinline__ void ldsm4(uint32_t addr, uint32_t& r0, uint32_t& r1,
                                      uint32_t& r2, uint32_t& r3) {
    asm volatile("ldmatrix.sync.aligned.m8n8.x4.shared.b16 {%0,%1,%2,%3}, [%4];"
                 : "=r"(r0), "=r"(r1), "=r"(r2), "=r"(r3) : "r"(addr));
}

__device__ __forceinline__ void mma16816(float* d, const uint32_t* a,
                                         const uint32_t* b) {
    asm volatile(
        "mma.sync.aligned.m16n8k16.row.col.f32.f16.f16.f32 "
        "{%0,%1,%2,%3}, {%4,%5,%6,%7}, {%8,%9}, {%0,%1,%2,%3};"
        : "+f"(d[0]), "+f"(d[1]), "+f"(d[2]), "+f"(d[3])
        : "r"(a[0]), "r"(a[1]), "r"(a[2]), "r"(a[3]), "r"(b[0]), "r"(b[1]));
}

__device__ __forceinline__ uint32_t swz(uint32_t off) {
    return off ^ ((off >> 3) & 0x70);
}

__device__ __forceinline__ void split2h(float a, float b,
                                        uint32_t& hi, uint32_t& lo) {
    __half ha = __float2half_rn(a);
    __half hb = __float2half_rn(b);
    __half la = __float2half_rn(a - __half2float(ha));
    __half lb = __float2half_rn(b - __half2float(hb));
    __half2 H = __halves2half2(ha, hb);
    __half2 L = __halves2half2(la, lb);
    hi = *(uint32_t*)&H;
    lo = *(uint32_t*)&L;
}

__device__ __forceinline__ uint32_t pack2h(float a, float b) {
    __half2 H = __floats2half2_rn(a, b);
    return *(uint32_t*)&H;
}

// ---------------------------------------------------------------------------
// conversion kernels
// ---------------------------------------------------------------------------
__global__ void split_fp16x2(const float* __restrict__ x,
                             __half* __restrict__ h,
                             __half* __restrict__ l, int n)
{
    int i = (blockIdx.x * 256 + threadIdx.x) * 4;
    if (i >= n) return;
    float4 v = *(const float4*)(x + i);
    uint32_t h01, l01, h23, l23;
    split2h(v.x, v.y, h01, l01);
    split2h(v.z, v.w, h23, l23);
    *(uint32_t*)(h + i)     = h01;
    *(uint32_t*)(h + i + 2) = h23;
    *(uint32_t*)(l + i)     = l01;
    *(uint32_t*)(l + i + 2) = l23;
}

__global__ void weights_to_fp16(const float* __restrict__ Wq,
                                const float* __restrict__ Wk,
                                const float* __restrict__ Wv,
                                const float* __restrict__ Wo,
                                __half* __restrict__ w, int NW)
{
    int i = (blockIdx.x * 256 + threadIdx.x) * 4;
    int which = i / NW;
    int off = i - which * NW;
    const float* src = (which == 0) ? Wq : (which == 1) ? Wk
                     : (which == 2) ? Wv : Wo;
    float4 v = *(const float4*)(src + off);
    *(uint32_t*)(w + i)     = pack2h(v.x, v.y);
    *(uint32_t*)(w + i + 2) = pack2h(v.z, v.w);
}

// ---------------------------------------------------------------------------
// HMMA GEMM (NT): out = alpha * ((Ah [+ Al]) @ B^T + bias), NPROD in {1,2}.
// 128x128 CTA tile, 8 warps (64x32), K chunks of 64, 2-stage cp.async,
// 2 CTAs/SM. smem stage layout: Ah@0 (16K), B@16K (16K), Al@32K (NPROD==2).
// Al fragment address = Ah fragment address + 32768 (NOT +16384 — that is
// the B tile; round-7 bug).
// Swizzle invariant: per-k-step offset (bits 5-6) applied with XOR (see R3).
// ---------------------------------------------------------------------------
#define GK_SMEM(npr) ((npr) == 2 ? (2 * 49152 + 1024) : (2 * 32768 + 1024))

template<int NPROD>
__device__ __forceinline__ void load_chunk(uint32_t stg, const __half* tAh,
                                           const __half* tAl, const __half* tBs,
                                           int K, int k0, int tid)
{
#pragma unroll
    for (int i = 0; i < 4; i++) {
        int s   = tid + i * 256;
        int row = s >> 3;
        int cb  = (s & 7) * 16;
        uint32_t sw = swz((uint32_t)(row * 128 + cb));
        size_t ge = (size_t)row * K + k0 + (cb >> 1);
        cp_async16(stg + sw,         tAh + ge);
        cp_async16(stg + 16384 + sw, tBs + ge);
        if (NPROD == 2) cp_async16(stg + 32768 + sw, tAl + ge);
    }
    CP_COMMIT();
}

template<int NPROD>
__global__ __launch_bounds__(256, 2)
void gemm_fp16(const __half* __restrict__ Ah,
               const __half* __restrict__ Al,
               const __half* __restrict__ Bs,
               const float* __restrict__ bias,
               float* __restrict__ Cf,
               __half* __restrict__ Ch,
               __half* __restrict__ Cl,
               int K, int N, float alpha)
{
    extern __shared__ char dsm[];
    const uint32_t sbase = (smem_u32(dsm) + 1023u) & ~1023u;
    const uint32_t STAGE = (NPROD == 2) ? 49152u : 32768u;

    const int tid = threadIdx.x;
    const int wid = tid >> 5;
    const int lane = tid & 31;
    const int wm = wid & 1;
    const int wn = wid >> 1;
    const int rowBase = blockIdx.y * 128;
    const int colBase = blockIdx.x * 128;

    const __half* tAh = Ah + (size_t)rowBase * K;
    const __half* tAl = Al + (size_t)rowBase * K;
    const __half* tBs = Bs + (size_t)colBase * K;

    float acc[4][4][4];
#pragma unroll
    for (int mf = 0; mf < 4; mf++)
#pragma unroll
        for (int nf = 0; nf < 4; nf++)
#pragma unroll
            for (int e = 0; e < 4; e++) acc[mf][nf][e] = 0.f;

    const uint32_t a_off = swz((uint32_t)((lane & 15) * 128 + ((lane >> 4) << 4)));
    const uint32_t b_off = swz((uint32_t)(
        (((lane >> 4) << 3) + (lane & 7)) * 128 + (((lane >> 3) & 1) << 4)));

    const int NCH = K >> 6;      // 16
    load_chunk<NPROD>(sbase, tAh, tAl, tBs, K, 0, tid);

    for (int k = 0; k < NCH; k++) {
        if (k + 1 < NCH) {
            load_chunk<NPROD>(sbase + ((k + 1) & 1) * STAGE,
                              tAh, tAl, tBs, K, (k + 1) * 64, tid);
            CP_WAIT(1);
        } else {
            CP_WAIT(0);
        }
        __syncthreads();   // chunk k data visible to all warps

        const uint32_t st = sbase + (uint32_t)(k & 1) * STAGE;
        const uint32_t aBase = st + (uint32_t)(wm * 64 * 128) + a_off;
        const uint32_t bBase = st + 16384 + (uint32_t)(wn * 32 * 128) + b_off;

#pragma unroll
        for (int ks = 0; ks < 4; ks++) {
            const uint32_t kOff = (uint32_t)(ks * 32);   // bits 5-6 -> XOR
            uint32_t bf[4][2];
#pragma unroll
            for (int p = 0; p < 2; p++) {
                uint32_t addr = (bBase + (uint32_t)(p * 16 * 128)) ^ kOff;
                ldsm4(addr, bf[2 * p][0], bf[2 * p][1],
                            bf[2 * p + 1][0], bf[2 * p + 1][1]);
            }
#pragma unroll
            for (int mf = 0; mf < 4; mf++) {
                uint32_t addr = (aBase + (uint32_t)(mf * 16 * 128)) ^ kOff;
                uint32_t ah4[4];
                ldsm4(addr, ah4[0], ah4[1], ah4[2], ah4[3]);
                if (NPROD == 2) {
                    uint32_t al4[4];
                    ldsm4(addr + 32768, al4[0], al4[1], al4[2], al4[3]);
#pragma unroll
                    for (int nf = 0; nf < 4; nf++) {
                        mma16816(acc[mf][nf], ah4, bf[nf]);
                        mma16816(acc[mf][nf], al4, bf[nf]);
                    }
                } else {
#pragma unroll
                    for (int nf = 0; nf < 4; nf++)
                        mma16816(acc[mf][nf], ah4, bf[nf]);
                }
            }
        }
        __syncthreads();   // all warps done with stage k before it is reloaded
    }

    const int g  = lane >> 2;
    const int t4 = lane & 3;
#pragma unroll
    for (int mf = 0; mf < 4; mf++) {
#pragma unroll
        for (int nf = 0; nf < 4; nf++) {
            const int r0 = rowBase + wm * 64 + mf * 16 + g;
            const int c0 = colBase + wn * 32 + nf * 8 + t4 * 2;
            float b0 = 0.f, b1 = 0.f;
            if (bias) { b0 = bias[c0]; b1 = bias[c0 + 1]; }
            float v0 = alpha * (acc[mf][nf][0] + b0);
            float v1 = alpha * (acc[mf][nf][1] + b1);
            float v2 = alpha * (acc[mf][nf][2] + b0);
            float v3 = alpha * (acc[mf][nf][3] + b1);
            if (Cf) {
                float2 o0, o1;
                o0.x = v0; o0.y = v1;
                o1.x = v2; o1.y = v3;
                *(float2*)(Cf + (size_t)r0 * N + c0)       = o0;
                *(float2*)(Cf + (size_t)(r0 + 8) * N + c0) = o1;
            } else if (Cl) {
                uint32_t h0, l0, h1, l1;
                split2h(v0, v1, h0, l0);
                split2h(v2, v3, h1, l1);
                *(uint32_t*)(Ch + (size_t)r0 * N + c0)       = h0;
                *(uint32_t*)(Cl + (size_t)r0 * N + c0)       = l0;
                *(uint32_t*)(Ch + (size_t)(r0 + 8) * N + c0) = h1;
                *(uint32_t*)(Cl + (size_t)(r0 + 8) * N + c0) = l1;
            } else {
                *(uint32_t*)(Ch + (size_t)r0 * N + c0)       = pack2h(v0, v1);
                *(uint32_t*)(Ch + (size_t)(r0 + 8) * N + c0) = pack2h(v2, v3);
            }
        }
    }
}

// ---------------------------------------------------------------------------
// Block-local attention on HMMA, fp16x2 scheme (unchanged from round 6).
// smem: qh@0 ql@16K k@32K vT@48K = 64 KB.
// ---------------------------------------------------------------------------
#define ATT_SMEM (64 * 1024 + 1024)

__global__ __launch_bounds__(256)
void block_attn_mma(const __half* __restrict__ Qh,
                    const __half* __restrict__ Ql,
                    const __half* __restrict__ Ks,
                    const __half* __restrict__ Vs,
                    __half* __restrict__ Oh,
                    __half* __restrict__ Ol)
{
    extern __shared__ char dsm[];
    const uint32_t sb0 = smem_u32(dsm);
    const uint32_t sbase = (sb0 + 1023u) & ~1023u;
    char* dsa = dsm + (sbase - sb0);

    const int tid = threadIdx.x;
    const int wid = tid >> 5;
    const int lane = tid & 31;

    const int idx = blockIdx.x;
    const int h = idx & 15, n = (idx >> 4) & 31, b = idx >> 9;
    const size_t base = ((size_t)b * 4096 + (size_t)n * 128) * 1024 + (size_t)h * 64;

    const uint32_t QH = 0, QL = 16384, KS = 32768, VT = 49152;

    for (int i = tid; i < 1024; i += 256) {
        int row = i >> 3;
        int cb = (i & 7) * 16;
        uint32_t sw = swz((uint32_t)(row * 128 + cb));
        size_t ge = base + (size_t)row * 1024 + (cb >> 1);
        cp_async16(sbase + QH + sw, Qh + ge);
        cp_async16(sbase + QL + sw, Ql + ge);
        cp_async16(sbase + KS + sw, Ks + ge);
    }
    CP_COMMIT();

    for (int i = tid; i < 1024; i += 256) {
        int j = i >> 3;
        int d0 = (i & 7) * 8;
        size_t ge = base + (size_t)j * 1024 + d0;
        uint4 hv = *(const uint4*)(Vs + ge);
        const __half* h8 = (const __half*)&hv;
        uint32_t tb = (uint32_t)((j >> 6) * 8192);
        int jl = j & 63;
#pragma unroll
        for (int e = 0; e < 8; e++) {
            uint32_t off = swz((uint32_t)((d0 + e) * 128 + jl * 2));
            *(__half*)(dsa + VT + tb + off) = h8[e];
        }
    }
    CP_WAIT(0);
    __syncthreads();

    const uint32_t a_off = swz((uint32_t)((lane & 15) * 128 + ((lane >> 4) << 4)));
    const uint32_t b_off = swz((uint32_t)(
        (((lane >> 4) << 3) + (lane & 7)) * 128 + (((lane >> 3) & 1) << 4)));

    float s[16][4];
#pragma unroll
    for (int nf = 0; nf < 16; nf++)
#pragma unroll
        for (int e = 0; e < 4; e++) s[nf][e] = 0.f;

    const uint32_t aQ = sbase + QH + (uint32_t)(wid * 16 * 128) + a_off;
#pragma unroll
    for (int ks = 0; ks < 4; ks++) {
        const uint32_t kOff = (uint32_t)(ks * 32);
        uint32_t qh4[4], ql4[4];
        ldsm4(aQ ^ kOff, qh4[0], qh4[1], qh4[2], qh4[3]);
        ldsm4((aQ ^ kOff) + 16384, ql4[0], ql4[1], ql4[2], ql4[3]);
#pragma unroll
        for (int p = 0; p < 8; p++) {
            uint32_t ab = (sbase + KS + (uint32_t)(p * 16 * 128) + b_off) ^ kOff;
            uint32_t bk[2][2];
            ldsm4(ab, bk[0][0], bk[0][1], bk[1][0], bk[1][1]);
            mma16816(s[2 * p],     qh4, bk[0]);
            mma16816(s[2 * p],     ql4, bk[0]);
            mma16816(s[2 * p + 1], qh4, bk[1]);
            mma16816(s[2 * p + 1], ql4, bk[1]);
        }
    }

    float m0 = -CUDART_INF_F, m1 = -CUDART_INF_F;
#pragma unroll
    for (int nf = 0; nf < 16; nf++) {
        m0 = fmaxf(m0, fmaxf(s[nf][0], s[nf][1]));
        m1 = fmaxf(m1, fmaxf(s[nf][2], s[nf][3]));
    }
    m0 = fmaxf(m0, __shfl_xor_sync(0xFFFFFFFFu, m0, 1));
    m0 = fmaxf(m0, __shfl_xor_sync(0xFFFFFFFFu, m0, 2));
    m1 = fmaxf(m1, __shfl_xor_sync(0xFFFFFFFFu, m1, 1));
    m1 = fmaxf(m1, __shfl_xor_sync(0xFFFFFFFFu, m1, 2));

    float sum0 = 0.f, sum1 = 0.f;
#pragma unroll
    for (int nf = 0; nf < 16; nf++) {
        s[nf][0] = __expf(s[nf][0] - m0); sum0 += s[nf][0];
        s[nf][1] = __expf(s[nf][1] - m0); sum0 += s[nf][1];
        s[nf][2] = __expf(s[nf][2] - m1); sum1 += s[nf][2];
        s[nf][3] = __expf(s[nf][3] - m1); sum1 += s[nf][3];
    }
    sum0 += __shfl_xor_sync(0xFFFFFFFFu, sum0, 1);
    sum0 += __shfl_xor_sync(0xFFFFFFFFu, sum0, 2);
    sum1 += __shfl_xor_sync(0xFFFFFFFFu, sum1, 1);
    sum1 += __shfl_xor_sync(0xFFFFFFFFu, sum1, 2);
    const float inv0 = 1.f / sum0;
    const float inv1 = 1.f / sum1;

    uint32_t ph[16][2], pl[16][2];
#pragma unroll
    for (int nf = 0; nf < 16; nf++) {
        split2h(s[nf][0] * inv0, s[nf][1] * inv0, ph[nf][0], pl[nf][0]);
        split2h(s[nf][2] * inv1, s[nf][3] * inv1, ph[nf][1], pl[nf][1]);
    }

    float o[8][4];
#pragma unroll
    for (int nf = 0; nf < 8; nf++)
#pragma unroll
        for (int e = 0; e < 4; e++) o[nf][e] = 0.f;

#pragma unroll
    for (int ks = 0; ks < 8; ks++) {
        uint32_t pa[4]  = { ph[2 * ks][0], ph[2 * ks][1],
                            ph[2 * ks + 1][0], ph[2 * ks + 1][1] };
        uint32_t pla[4] = { pl[2 * ks][0], pl[2 * ks][1],
                            pl[2 * ks + 1][0], pl[2 * ks + 1][1] };
        const uint32_t tb = sbase + VT + (uint32_t)((ks >> 2) * 8192);
        const uint32_t kOff = (uint32_t)((ks & 3) * 32);
#pragma unroll
        for (int p = 0; p < 4; p++) {
            uint32_t ab = (tb + (uint32_t)(p * 16 * 128) + b_off) ^ kOff;
            uint32_t bv[2][2];
            ldsm4(ab, bv[0][0], bv[0][1], bv[1][0], bv[1][1]);
            mma16816(o[2 * p],     pa,  bv[0]);
            mma16816(o[2 * p],     pla, bv[0]);
            mma16816(o[2 * p + 1], pa,  bv[1]);
            mma16816(o[2 * p + 1], pla, bv[1]);
        }
    }

    const int g = lane >> 2, t4 = lane & 3;
#pragma unroll
    for (int nf = 0; nf < 8; nf++) {
        const int r0 = wid * 16 + g;
        const int c  = nf * 8 + t4 * 2;
        const size_t e0 = base + (size_t)r0 * 1024 + c;
        const size_t e1 = base + (size_t)(r0 + 8) * 1024 + c;
        uint32_t h0, l0, h1, l1;
        split2h(o[nf][0], o[nf][1], h0, l0);
        split2h(o[nf][2], o[nf][3], h1, l1);
        *(uint32_t*)(Oh + e0) = h0;
        *(uint32_t*)(Ol + e0) = l0;
        *(uint32_t*)(Oh + e1) = h1;
        *(uint32_t*)(Ol + e1) = l1;
    }
}

// ---------------------------------------------------------------------------
extern "C" void kernel_launch(void* const* d_in, const int* in_sizes, int n_in,
                              void* d_out, int out_size)
{
    const float* x  = (const float*)d_in[0];
    const float* Wq = (const float*)d_in[1];
    const float* bq = (const float*)d_in[2];
    const float* Wk = (const float*)d_in[3];
    const float* Wv = (const float*)d_in[4];
    const float* bv = (const float*)d_in[5];
    const float* Wo = (const float*)d_in[6];
    const float* bo = (const float*)d_in[7];
    float* out = (float*)d_out;

    __half *xh, *xl, *qh, *ql, *ks, *vs, *ah, *al, *w;
    cudaGetSymbolAddress((void**)&xh, g_xh);
    cudaGetSymbolAddress((void**)&xl, g_xl);
    cudaGetSymbolAddress((void**)&qh, g_qh);
    cudaGetSymbolAddress((void**)&ql, g_ql);
    cudaGetSymbolAddress((void**)&ks, g_ks);
    cudaGetSymbolAddress((void**)&vs, g_vs);
    cudaGetSymbolAddress((void**)&ah, g_ah);
    cudaGetSymbolAddress((void**)&al, g_al);
    cudaGetSymbolAddress((void**)&w,  g_w);

    cudaFuncSetAttribute(gemm_fp16<2>,
                         cudaFuncAttributeMaxDynamicSharedMemorySize, GK_SMEM(2));
    cudaFuncSetAttribute(gemm_fp16<1>,
                         cudaFuncAttributeMaxDynamicSharedMemorySize, GK_SMEM(1));
    cudaFuncSetAttribute(block_attn_mma,
                         cudaFuncAttributeMaxDynamicSharedMemorySize, ATT_SMEM);

    const int NX = M_ROWS * CDIM;
    const int NW = CDIM * CDIM;

    split_fp16x2<<<NX / 4 / 256, 256>>>(x, xh, xl, NX);
    weights_to_fp16<<<4 * NW / 4 / 256, 256>>>(Wq, Wk, Wv, Wo, w, NW);

    const dim3 ggrid(CDIM / 128, M_ROWS / 128);   // (8, 128)

    // q: fp16x2 (split output); k,v: fp16x1 (single fp16 output)
    gemm_fp16<2><<<ggrid, 256, GK_SMEM(2)>>>(xh, xl, w + 0 * NW, bq,
                                             nullptr, qh, ql, CDIM, CDIM, QK_SCALE);
    gemm_fp16<1><<<ggrid, 256, GK_SMEM(1)>>>(xh, xh, w + 1 * NW, nullptr,
                                             nullptr, ks, nullptr, CDIM, CDIM, QK_SCALE);
    gemm_fp16<1><<<ggrid, 256, GK_SMEM(1)>>>(xh, xh, w + 2 * NW, bv,
                                             nullptr, vs, nullptr, CDIM, CDIM, 1.0f);

    block_attn_mma<<<2048, 256, ATT_SMEM>>>(qh, ql, ks, vs, ah, al);

    // out: fp16x2 -> fp32
    gemm_fp16<2><<<ggrid, 256, GK_SMEM(2)>>>(ah, al, w + 3 * NW, bo,
                                             out, nullptr, nullptr, CDIM, CDIM, 1.0f);
}

// round 9
// speedup vs baseline: 9.4342x; 1.3799x over previous
#include <cuda_runtime.h>
#include <cuda_fp16.h>
#include <math_constants.h>
#include <cstdint>

// ---------------------------------------------------------------------------
// MultiHeadAttention (block-local). All matmuls on HMMA (mma.sync m16n8k16
// fp16, fp32 acc), all operands single fp16 except P in the PV product
// (split hi/lo in registers, free). Error budget ~11 incoherent 2^-12
// sources => rel_err ~4.6e-4 (threshold 1e-3).
// Shapes: B=4, T=4096, C=1024, H=16, HD=64, NBLOCKS=32, BSIZE=128
// ---------------------------------------------------------------------------

#define M_ROWS 16384
#define CDIM   1024
#define QK_SCALE 0.35355339059327376f   // 64^(-0.25)

__device__ __align__(256) __half g_x[M_ROWS * CDIM];
__device__ __align__(256) __half g_q[M_ROWS * CDIM];
__device__ __align__(256) __half g_k[M_ROWS * CDIM];
__device__ __align__(256) __half g_v[M_ROWS * CDIM];
__device__ __align__(256) __half g_a[M_ROWS * CDIM];
__device__ __align__(256) __half g_w[4 * CDIM * CDIM];

// ---------------------------------------------------------------------------
// helpers
// ---------------------------------------------------------------------------
__device__ __forceinline__ uint32_t smem_u32(const void* p) {
    uint32_t a;
    asm("{ .reg .u64 t; cvta.to.shared.u64 t, %1; cvt.u32.u64 %0, t; }"
        : "=r"(a) : "l"(p));
    return a;
}

__device__ __forceinline__ void cp_async16(uint32_t dst, const void* src) {
    asm volatile("cp.async.cg.shared.global [%0], [%1], 16;"
                 :: "r"(dst), "l"(src));
}
#define CP_COMMIT() asm volatile("cp.async.commit_group;" ::: "memory")
#define CP_WAIT(n)  asm volatile("cp.async.wait_group %0;" :: "n"(n) : "memory")

__device__ __forceinline__ void ldsm4(uint32_t addr, uint32_t& r0, uint32_t& r1,
                                      uint32_t& r2, uint32_t& r3) {
    asm volatile("ldmatrix.sync.aligned.m8n8.x4.shared.b16 {%0,%1,%2,%3}, [%4];"
                 : "=r"(r0), "=r"(r1), "=r"(r2), "=r"(r3) : "r"(addr));
}

__device__ __forceinline__ void mma16816(float* d, const uint32_t* a,
                                         const uint32_t* b) {
    asm volatile(
        "mma.sync.aligned.m16n8k16.row.col.f32.f16.f16.f32 "
        "{%0,%1,%2,%3}, {%4,%5,%6,%7}, {%8,%9}, {%0,%1,%2,%3};"
        : "+f"(d[0]), "+f"(d[1]), "+f"(d[2]), "+f"(d[3])
        : "r"(a[0]), "r"(a[1]), "r"(a[2]), "r"(a[3]), "r"(b[0]), "r"(b[1]));
}

__device__ __forceinline__ uint32_t swz(uint32_t off) {
    return off ^ ((off >> 3) & 0x70);
}

__device__ __forceinline__ void split2h(float a, float b,
                                        uint32_t& hi, uint32_t& lo) {
    __half ha = __float2half_rn(a);
    __half hb = __float2half_rn(b);
    __half la = __float2half_rn(a - __half2float(ha));
    __half lb = __float2half_rn(b - __half2float(hb));
    __half2 H = __halves2half2(ha, hb);
    __half2 L = __halves2half2(la, lb);
    hi = *(uint32_t*)&H;
    lo = *(uint32_t*)&L;
}

__device__ __forceinline__ uint32_t pack2h(float a, float b) {
    __half2 H = __floats2half2_rn(a, b);
    return *(uint32_t*)&H;
}

// ---------------------------------------------------------------------------
// conversion kernels
// ---------------------------------------------------------------------------
__global__ void to_fp16(const float* __restrict__ x,
                        __half* __restrict__ h, int n)
{
    int i = (blockIdx.x * 256 + threadIdx.x) * 4;
    if (i >= n) return;
    float4 v = *(const float4*)(x + i);
    *(uint32_t*)(h + i)     = pack2h(v.x, v.y);
    *(uint32_t*)(h + i + 2) = pack2h(v.z, v.w);
}

__global__ void weights_to_fp16(const float* __restrict__ Wq,
                                const float* __restrict__ Wk,
                                const float* __restrict__ Wv,
                                const float* __restrict__ Wo,
                                __half* __restrict__ w, int NW)
{
    int i = (blockIdx.x * 256 + threadIdx.x) * 4;
    int which = i / NW;
    int off = i - which * NW;
    const float* src = (which == 0) ? Wq : (which == 1) ? Wk
                     : (which == 2) ? Wv : Wo;
    float4 v = *(const float4*)(src + off);
    *(uint32_t*)(w + i)     = pack2h(v.x, v.y);
    *(uint32_t*)(w + i + 2) = pack2h(v.z, v.w);
}

// ---------------------------------------------------------------------------
// HMMA fp16 GEMM (NT): out = alpha * (A @ B^T + bias).
// 128x128 CTA tile, 8 warps (64x32), K chunks of 64, 3-stage cp.async ring,
// ONE __syncthreads per chunk, 2 CTAs/SM.
// Stage layout: A@0 (16K), B@16K (16K). Safety argument for the single sync:
// the load of chunk k+2 (buffer (k-1)%3) is issued after sync k, at which
// point every warp has finished iteration k-1 (compute of buffer (k-1)%3).
// Swizzle invariant: per-k-step offset (bits 5-6) applied with XOR (see R3).
// ---------------------------------------------------------------------------
#define GK_STAGE 32768
#define GK_SMEM  (3 * GK_STAGE + 1024)

__device__ __forceinline__ void load_chunk(uint32_t stg, const __half* tA,
                                           const __half* tB,
                                           int K, int k0, int tid)
{
#pragma unroll
    for (int i = 0; i < 4; i++) {
        int s   = tid + i * 256;
        int row = s >> 3;
        int cb  = (s & 7) * 16;
        uint32_t sw = swz((uint32_t)(row * 128 + cb));
        size_t ge = (size_t)row * K + k0 + (cb >> 1);
        cp_async16(stg + sw,         tA + ge);
        cp_async16(stg + 16384 + sw, tB + ge);
    }
    CP_COMMIT();
}

__global__ __launch_bounds__(256, 2)
void gemm_fp16(const __half* __restrict__ A,
               const __half* __restrict__ Bs,
               const float* __restrict__ bias,
               float* __restrict__ Cf,
               __half* __restrict__ Ch,
               int K, int N, float alpha)
{
    extern __shared__ char dsm[];
    const uint32_t sbase = (smem_u32(dsm) + 1023u) & ~1023u;

    const int tid = threadIdx.x;
    const int wid = tid >> 5;
    const int lane = tid & 31;
    const int wm = wid & 1;
    const int wn = wid >> 1;
    const int rowBase = blockIdx.y * 128;
    const int colBase = blockIdx.x * 128;

    const __half* tA = A  + (size_t)rowBase * K;
    const __half* tB = Bs + (size_t)colBase * K;

    float acc[4][4][4];
#pragma unroll
    for (int mf = 0; mf < 4; mf++)
#pragma unroll
        for (int nf = 0; nf < 4; nf++)
#pragma unroll
            for (int e = 0; e < 4; e++) acc[mf][nf][e] = 0.f;

    const uint32_t a_off = swz((uint32_t)((lane & 15) * 128 + ((lane >> 4) << 4)));
    const uint32_t b_off = swz((uint32_t)(
        (((lane >> 4) << 3) + (lane & 7)) * 128 + (((lane >> 3) & 1) << 4)));

    const int NCH = K >> 6;      // 16
    load_chunk(sbase,            tA, tB, K, 0, tid);
    load_chunk(sbase + GK_STAGE, tA, tB, K, 64, tid);

    for (int k = 0; k < NCH; k++) {
        if (k + 1 < NCH) CP_WAIT(1); else CP_WAIT(0);   // chunk k arrived
        __syncthreads();                                 // visible to all

        const uint32_t st = sbase + (uint32_t)(k % 3) * GK_STAGE;
        const uint32_t aBase = st + (uint32_t)(wm * 64 * 128) + a_off;
        const uint32_t bBase = st + 16384 + (uint32_t)(wn * 32 * 128) + b_off;

#pragma unroll
        for (int ks = 0; ks < 4; ks++) {
            const uint32_t kOff = (uint32_t)(ks * 32);   // bits 5-6 -> XOR
            uint32_t bf[4][2];
#pragma unroll
            for (int p = 0; p < 2; p++) {
                uint32_t addr = (bBase + (uint32_t)(p * 16 * 128)) ^ kOff;
                ldsm4(addr, bf[2 * p][0], bf[2 * p][1],
                            bf[2 * p + 1][0], bf[2 * p + 1][1]);
            }
#pragma unroll
            for (int mf = 0; mf < 4; mf++) {
                uint32_t addr = (aBase + (uint32_t)(mf * 16 * 128)) ^ kOff;
                uint32_t a4[4];
                ldsm4(addr, a4[0], a4[1], a4[2], a4[3]);
#pragma unroll
                for (int nf = 0; nf < 4; nf++)
                    mma16816(acc[mf][nf], a4, bf[nf]);
            }
        }

        // prefetch chunk k+2 into buffer (k+2)%3 == (k-1)%3 (safe post-sync)
        if (k + 2 < NCH)
            load_chunk(sbase + (uint32_t)((k + 2) % 3) * GK_STAGE,
                       tA, tB, K, (k + 2) * 64, tid);
    }

    const int g  = lane >> 2;
    const int t4 = lane & 3;
#pragma unroll
    for (int mf = 0; mf < 4; mf++) {
#pragma unroll
        for (int nf = 0; nf < 4; nf++) {
            const int r0 = rowBase + wm * 64 + mf * 16 + g;
            const int c0 = colBase + wn * 32 + nf * 8 + t4 * 2;
            float b0 = 0.f, b1 = 0.f;
            if (bias) { b0 = bias[c0]; b1 = bias[c0 + 1]; }
            float v0 = alpha * (acc[mf][nf][0] + b0);
            float v1 = alpha * (acc[mf][nf][1] + b1);
            float v2 = alpha * (acc[mf][nf][2] + b0);
            float v3 = alpha * (acc[mf][nf][3] + b1);
            if (Cf) {
                float2 o0, o1;
                o0.x = v0; o0.y = v1;
                o1.x = v2; o1.y = v3;
                *(float2*)(Cf + (size_t)r0 * N + c0)       = o0;
                *(float2*)(Cf + (size_t)(r0 + 8) * N + c0) = o1;
            } else {
                *(uint32_t*)(Ch + (size_t)r0 * N + c0)       = pack2h(v0, v1);
                *(uint32_t*)(Ch + (size_t)(r0 + 8) * N + c0) = pack2h(v2, v3);
            }
        }
    }
}

// ---------------------------------------------------------------------------
// Block-local attention on HMMA. q,k,v single fp16; P split hi/lo in regs.
// smem: q@0 (16K), k@16K (16K), vT@32K (two [64][64] tiles) = 48 KB.
// ---------------------------------------------------------------------------
#define ATT_SMEM (48 * 1024 + 1024)

__global__ __launch_bounds__(256)
void block_attn_mma(const __half* __restrict__ Q,
                    const __half* __restrict__ K,
                    const __half* __restrict__ V,
                    __half* __restrict__ Oa)
{
    extern __shared__ char dsm[];
    const uint32_t sb0 = smem_u32(dsm);
    const uint32_t sbase = (sb0 + 1023u) & ~1023u;
    char* dsa = dsm + (sbase - sb0);

    const int tid = threadIdx.x;
    const int wid = tid >> 5;
    const int lane = tid & 31;

    const int idx = blockIdx.x;
    const int h = idx & 15, n = (idx >> 4) & 31, b = idx >> 9;
    const size_t base = ((size_t)b * 4096 + (size_t)n * 128) * 1024 + (size_t)h * 64;

    const uint32_t QS = 0, KS = 16384, VT = 32768;

    for (int i = tid; i < 1024; i += 256) {
        int row = i >> 3;
        int cb = (i & 7) * 16;
        uint32_t sw = swz((uint32_t)(row * 128 + cb));
        size_t ge = base + (size_t)row * 1024 + (cb >> 1);
        cp_async16(sbase + QS + sw, Q + ge);
        cp_async16(sbase + KS + sw, K + ge);
    }
    CP_COMMIT();

    for (int i = tid; i < 1024; i += 256) {
        int j = i >> 3;
        int d0 = (i & 7) * 8;
        size_t ge = base + (size_t)j * 1024 + d0;
        uint4 hv = *(const uint4*)(V + ge);
        const __half* h8 = (const __half*)&hv;
        uint32_t tb = (uint32_t)((j >> 6) * 8192);
        int jl = j & 63;
#pragma unroll
        for (int e = 0; e < 8; e++) {
            uint32_t off = swz((uint32_t)((d0 + e) * 128 + jl * 2));
            *(__half*)(dsa + VT + tb + off) = h8[e];
        }
    }
    CP_WAIT(0);
    __syncthreads();

    const uint32_t a_off = swz((uint32_t)((lane & 15) * 128 + ((lane >> 4) << 4)));
    const uint32_t b_off = swz((uint32_t)(
        (((lane >> 4) << 3) + (lane & 7)) * 128 + (((lane >> 3) & 1) << 4)));

    float s[16][4];
#pragma unroll
    for (int nf = 0; nf < 16; nf++)
#pragma unroll
        for (int e = 0; e < 4; e++) s[nf][e] = 0.f;

    const uint32_t aQ = sbase + QS + (uint32_t)(wid * 16 * 128) + a_off;
#pragma unroll
    for (int ks = 0; ks < 4; ks++) {
        const uint32_t kOff = (uint32_t)(ks * 32);
        uint32_t q4[4];
        ldsm4(aQ ^ kOff, q4[0], q4[1], q4[2], q4[3]);
#pragma unroll
        for (int p = 0; p < 8; p++) {
            uint32_t ab = (sbase + KS + (uint32_t)(p * 16 * 128) + b_off) ^ kOff;
            uint32_t bk[2][2];
            ldsm4(ab, bk[0][0], bk[0][1], bk[1][0], bk[1][1]);
            mma16816(s[2 * p],     q4, bk[0]);
            mma16816(s[2 * p + 1], q4, bk[1]);
        }
    }

    float m0 = -CUDART_INF_F, m1 = -CUDART_INF_F;
#pragma unroll
    for (int nf = 0; nf < 16; nf++) {
        m0 = fmaxf(m0, fmaxf(s[nf][0], s[nf][1]));
        m1 = fmaxf(m1, fmaxf(s[nf][2], s[nf][3]));
    }
    m0 = fmaxf(m0, __shfl_xor_sync(0xFFFFFFFFu, m0, 1));
    m0 = fmaxf(m0, __shfl_xor_sync(0xFFFFFFFFu, m0, 2));
    m1 = fmaxf(m1, __shfl_xor_sync(0xFFFFFFFFu, m1, 1));
    m1 = fmaxf(m1, __shfl_xor_sync(0xFFFFFFFFu, m1, 2));

    float sum0 = 0.f, sum1 = 0.f;
#pragma unroll
    for (int nf = 0; nf < 16; nf++) {
        s[nf][0] = __expf(s[nf][0] - m0); sum0 += s[nf][0];
        s[nf][1] = __expf(s[nf][1] - m0); sum0 += s[nf][1];
        s[nf][2] = __expf(s[nf][2] - m1); sum1 += s[nf][2];
        s[nf][3] = __expf(s[nf][3] - m1); sum1 += s[nf][3];
    }
    sum0 += __shfl_xor_sync(0xFFFFFFFFu, sum0, 1);
    sum0 += __shfl_xor_sync(0xFFFFFFFFu, sum0, 2);
    sum1 += __shfl_xor_sync(0xFFFFFFFFu, sum1, 1);
    sum1 += __shfl_xor_sync(0xFFFFFFFFu, sum1, 2);
    const float inv0 = 1.f / sum0;
    const float inv1 = 1.f / sum1;

    // P split hi/lo in registers (free precision for the PV product)
    uint32_t ph[16][2], pl[16][2];
#pragma unroll
    for (int nf = 0; nf < 16; nf++) {
        split2h(s[nf][0] * inv0, s[nf][1] * inv0, ph[nf][0], pl[nf][0]);
        split2h(s[nf][2] * inv1, s[nf][3] * inv1, ph[nf][1], pl[nf][1]);
    }

    float o[8][4];
#pragma unroll
    for (int nf = 0; nf < 8; nf++)
#pragma unroll
        for (int e = 0; e < 4; e++) o[nf][e] = 0.f;

#pragma unroll
    for (int ks = 0; ks < 8; ks++) {
        uint32_t pa[4]  = { ph[2 * ks][0], ph[2 * ks][1],
                            ph[2 * ks + 1][0], ph[2 * ks + 1][1] };
        uint32_t pla[4] = { pl[2 * ks][0], pl[2 * ks][1],
                            pl[2 * ks + 1][0], pl[2 * ks + 1][1] };
        const uint32_t tb = sbase + VT + (uint32_t)((ks >> 2) * 8192);
        const uint32_t kOff = (uint32_t)((ks & 3) * 32);
#pragma unroll
        for (int p = 0; p < 4; p++) {
            uint32_t ab = (tb + (uint32_t)(p * 16 * 128) + b_off) ^ kOff;
            uint32_t bv[2][2];
            ldsm4(ab, bv[0][0], bv[0][1], bv[1][0], bv[1][1]);
            mma16816(o[2 * p],     pa,  bv[0]);
            mma16816(o[2 * p],     pla, bv[0]);
            mma16816(o[2 * p + 1], pa,  bv[1]);
            mma16816(o[2 * p + 1], pla, bv[1]);
        }
    }

    const int g = lane >> 2, t4 = lane & 3;
#pragma unroll
    for (int nf = 0; nf < 8; nf++) {
        const int r0 = wid * 16 + g;
        const int c  = nf * 8 + t4 * 2;
        const size_t e0 = base + (size_t)r0 * 1024 + c;
        const size_t e1 = base + (size_t)(r0 + 8) * 1024 + c;
        *(uint32_t*)(Oa + e0) = pack2h(o[nf][0], o[nf][1]);
        *(uint32_t*)(Oa + e1) = pack2h(o[nf][2], o[nf][3]);
    }
}

// ---------------------------------------------------------------------------
extern "C" void kernel_launch(void* const* d_in, const int* in_sizes, int n_in,
                              void* d_out, int out_size)
{
    const float* x  = (const float*)d_in[0];
    const float* Wq = (const float*)d_in[1];
    const float* bq = (const float*)d_in[2];
    const float* Wk = (const float*)d_in[3];
    const float* Wv = (const float*)d_in[4];
    const float* bv = (const float*)d_in[5];
    const float* Wo = (const float*)d_in[6];
    const float* bo = (const float*)d_in[7];
    float* out = (float*)d_out;

    __half *xs, *qs, *ks, *vs, *as, *w;
    cudaGetSymbolAddress((void**)&xs, g_x);
    cudaGetSymbolAddress((void**)&qs, g_q);
    cudaGetSymbolAddress((void**)&ks, g_k);
    cudaGetSymbolAddress((void**)&vs, g_v);
    cudaGetSymbolAddress((void**)&as, g_a);
    cudaGetSymbolAddress((void**)&w,  g_w);

    cudaFuncSetAttribute(gemm_fp16,
                         cudaFuncAttributeMaxDynamicSharedMemorySize, GK_SMEM);
    cudaFuncSetAttribute(block_attn_mma,
                         cudaFuncAttributeMaxDynamicSharedMemorySize, ATT_SMEM);

    const int NX = M_ROWS * CDIM;
    const int NW = CDIM * CDIM;

    to_fp16<<<NX / 4 / 256, 256>>>(x, xs, NX);
    weights_to_fp16<<<4 * NW / 4 / 256, 256>>>(Wq, Wk, Wv, Wo, w, NW);

    const dim3 ggrid(CDIM / 128, M_ROWS / 128);   // (8, 128)

    gemm_fp16<<<ggrid, 256, GK_SMEM>>>(xs, w + 0 * NW, bq,
                                       nullptr, qs, CDIM, CDIM, QK_SCALE);
    gemm_fp16<<<ggrid, 256, GK_SMEM>>>(xs, w + 1 * NW, nullptr,
                                       nullptr, ks, CDIM, CDIM, QK_SCALE);
    gemm_fp16<<<ggrid, 256, GK_SMEM>>>(xs, w + 2 * NW, bv,
                                       nullptr, vs, CDIM, CDIM, 1.0f);

    block_attn_mma<<<2048, 256, ATT_SMEM>>>(qs, ks, vs, as);

    gemm_fp16<<<ggrid, 256, GK_SMEM>>>(as, w + 3 * NW, bo,
                                       out, nullptr, CDIM, CDIM, 1.0f);
}

// round 10
// speedup vs baseline: 9.5246x; 1.0096x over previous
#include <cuda_runtime.h>
#include <cuda_fp16.h>
#include <math_constants.h>
#include <cstdint>

// ---------------------------------------------------------------------------
// MultiHeadAttention (block-local). All matmuls on HMMA (mma.sync m16n8k16
// fp16, fp32 acc), all operands single fp16. q/k/v projections fused into
// one N=3072 GEMM (weights contiguous). Error budget ~12 incoherent 2^-12
// sources => rel_err ~4.4e-4 (threshold 1e-3).
// Shapes: B=4, T=4096, C=1024, H=16, HD=64, NBLOCKS=32, BSIZE=128
// ---------------------------------------------------------------------------

#define M_ROWS 16384
#define CDIM   1024
#define QK_SCALE 0.35355339059327376f   // 64^(-0.25)

__device__ __align__(256) __half g_x[M_ROWS * CDIM];
__device__ __align__(256) __half g_q[M_ROWS * CDIM];
__device__ __align__(256) __half g_k[M_ROWS * CDIM];
__device__ __align__(256) __half g_v[M_ROWS * CDIM];
__device__ __align__(256) __half g_a[M_ROWS * CDIM];
__device__ __align__(256) __half g_w[4 * CDIM * CDIM];

// ---------------------------------------------------------------------------
// helpers
// ---------------------------------------------------------------------------
__device__ __forceinline__ uint32_t smem_u32(const void* p) {
    uint32_t a;
    asm("{ .reg .u64 t; cvta.to.shared.u64 t, %1; cvt.u32.u64 %0, t; }"
        : "=r"(a) : "l"(p));
    return a;
}

__device__ __forceinline__ void cp_async16(uint32_t dst, const void* src) {
    asm volatile("cp.async.cg.shared.global [%0], [%1], 16;"
                 :: "r"(dst), "l"(src));
}
#define CP_COMMIT() asm volatile("cp.async.commit_group;" ::: "memory")
#define CP_WAIT(n)  asm volatile("cp.async.wait_group %0;" :: "n"(n) : "memory")

__device__ __forceinline__ void ldsm4(uint32_t addr, uint32_t& r0, uint32_t& r1,
                                      uint32_t& r2, uint32_t& r3) {
    asm volatile("ldmatrix.sync.aligned.m8n8.x4.shared.b16 {%0,%1,%2,%3}, [%4];"
                 : "=r"(r0), "=r"(r1), "=r"(r2), "=r"(r3) : "r"(addr));
}

__device__ __forceinline__ void mma16816(float* d, const uint32_t* a,
                                         const uint32_t* b) {
    asm volatile(
        "mma.sync.aligned.m16n8k16.row.col.f32.f16.f16.f32 "
        "{%0,%1,%2,%3}, {%4,%5,%6,%7}, {%8,%9}, {%0,%1,%2,%3};"
        : "+f"(d[0]), "+f"(d[1]), "+f"(d[2]), "+f"(d[3])
        : "r"(a[0]), "r"(a[1]), "r"(a[2]), "r"(a[3]), "r"(b[0]), "r"(b[1]));
}

__device__ __forceinline__ uint32_t swz(uint32_t off) {
    return off ^ ((off >> 3) & 0x70);
}

__device__ __forceinline__ uint32_t pack2h(float a, float b) {
    __half2 H = __floats2half2_rn(a, b);
    return *(uint32_t*)&H;
}

// ---------------------------------------------------------------------------
// conversion kernels
// ---------------------------------------------------------------------------
__global__ void to_fp16(const float* __restrict__ x,
                        __half* __restrict__ h, int n)
{
    int i = (blockIdx.x * 256 + threadIdx.x) * 4;
    if (i >= n) return;
    float4 v = *(const float4*)(x + i);
    *(uint32_t*)(h + i)     = pack2h(v.x, v.y);
    *(uint32_t*)(h + i + 2) = pack2h(v.z, v.w);
}

__global__ void weights_to_fp16(const float* __restrict__ Wq,
                                const float* __restrict__ Wk,
                                const float* __restrict__ Wv,
                                const float* __restrict__ Wo,
                                __half* __restrict__ w, int NW)
{
    int i = (blockIdx.x * 256 + threadIdx.x) * 4;
    int which = i / NW;
    int off = i - which * NW;
    const float* src = (which == 0) ? Wq : (which == 1) ? Wk
                     : (which == 2) ? Wv : Wo;
    float4 v = *(const float4*)(src + off);
    *(uint32_t*)(w + i)     = pack2h(v.x, v.y);
    *(uint32_t*)(w + i + 2) = pack2h(v.z, v.w);
}

// ---------------------------------------------------------------------------
// HMMA fp16 GEMM core: 128x128 CTA tile, 8 warps (64x32), K chunks of 64,
// 3-stage cp.async ring, one __syncthreads per chunk, 2 CTAs/SM.
// Stage layout: A@0 (16K), B@16K (16K).
// Swizzle invariant: per-k-step offset (bits 5-6) applied with XOR (see R3).
// ---------------------------------------------------------------------------
#define GK_STAGE 32768
#define GK_SMEM  (3 * GK_STAGE + 1024)

__device__ __forceinline__ void load_chunk(uint32_t stg, const __half* tA,
                                           const __half* tB,
                                           int K, int k0, int tid)
{
#pragma unroll
    for (int i = 0; i < 4; i++) {
        int s   = tid + i * 256;
        int row = s >> 3;
        int cb  = (s & 7) * 16;
        uint32_t sw = swz((uint32_t)(row * 128 + cb));
        size_t ge = (size_t)row * K + k0 + (cb >> 1);
        cp_async16(stg + sw,         tA + ge);
        cp_async16(stg + 16384 + sw, tB + ge);
    }
    CP_COMMIT();
}

// computes the 128x128 tile at (rowBase, colBase) of A[M,K] @ B[Ntot,K]^T
__device__ __forceinline__ void gemm_tile(const __half* A, const __half* Bs,
                                          int K, int rowBase, int colBase,
                                          float acc[4][4][4])
{
    extern __shared__ char dsm[];
    const uint32_t sbase = (smem_u32(dsm) + 1023u) & ~1023u;

    const int tid = threadIdx.x;
    const int wid = tid >> 5;
    const int lane = tid & 31;
    const int wm = wid & 1;
    const int wn = wid >> 1;

    const __half* tA = A  + (size_t)rowBase * K;
    const __half* tB = Bs + (size_t)colBase * K;

#pragma unroll
    for (int mf = 0; mf < 4; mf++)
#pragma unroll
        for (int nf = 0; nf < 4; nf++)
#pragma unroll
            for (int e = 0; e < 4; e++) acc[mf][nf][e] = 0.f;

    const uint32_t a_off = swz((uint32_t)((lane & 15) * 128 + ((lane >> 4) << 4)));
    const uint32_t b_off = swz((uint32_t)(
        (((lane >> 4) << 3) + (lane & 7)) * 128 + (((lane >> 3) & 1) << 4)));

    const int NCH = K >> 6;      // 16
    load_chunk(sbase,            tA, tB, K, 0, tid);
    load_chunk(sbase + GK_STAGE, tA, tB, K, 64, tid);

    for (int k = 0; k < NCH; k++) {
        if (k + 1 < NCH) CP_WAIT(1); else CP_WAIT(0);
        __syncthreads();

        const uint32_t st = sbase + (uint32_t)(k % 3) * GK_STAGE;
        const uint32_t aBase = st + (uint32_t)(wm * 64 * 128) + a_off;
        const uint32_t bBase = st + 16384 + (uint32_t)(wn * 32 * 128) + b_off;

#pragma unroll
        for (int ks = 0; ks < 4; ks++) {
            const uint32_t kOff = (uint32_t)(ks * 32);   // bits 5-6 -> XOR
            uint32_t bf[4][2];
#pragma unroll
            for (int p = 0; p < 2; p++) {
                uint32_t addr = (bBase + (uint32_t)(p * 16 * 128)) ^ kOff;
                ldsm4(addr, bf[2 * p][0], bf[2 * p][1],
                            bf[2 * p + 1][0], bf[2 * p + 1][1]);
            }
#pragma unroll
            for (int mf = 0; mf < 4; mf++) {
                uint32_t addr = (aBase + (uint32_t)(mf * 16 * 128)) ^ kOff;
                uint32_t a4[4];
                ldsm4(addr, a4[0], a4[1], a4[2], a4[3]);
#pragma unroll
                for (int nf = 0; nf < 4; nf++)
                    mma16816(acc[mf][nf], a4, bf[nf]);
            }
        }

        if (k + 2 < NCH)
            load_chunk(sbase + (uint32_t)((k + 2) % 3) * GK_STAGE,
                       tA, tB, K, (k + 2) * 64, tid);
    }
}

// fused q/k/v projection: B = [Wq;Wk;Wv] (3072 x 1024), per-column-block
// select of {alpha, bias, dst}. Outputs fp16, stride 1024.
__global__ __launch_bounds__(256, 2)
void gemm_qkv(const __half* __restrict__ X,
              const __half* __restrict__ W3,
              const float* __restrict__ bq,
              const float* __restrict__ bv,
              __half* __restrict__ Qo,
              __half* __restrict__ Ko,
              __half* __restrict__ Vo)
{
    const int rowBase = blockIdx.y * 128;
    const int colBase = blockIdx.x * 128;       // 0..2944
    float acc[4][4][4];
    gemm_tile(X, W3, CDIM, rowBase, colBase, acc);

    const int sel = colBase >> 10;
    const int c1k = colBase & 1023;
    __half* dst = (sel == 0) ? Qo : (sel == 1) ? Ko : Vo;
    const float* bias = (sel == 0) ? bq : (sel == 2) ? bv : nullptr;
    const float alpha = (sel == 2) ? 1.0f : QK_SCALE;

    const int lane = threadIdx.x & 31;
    const int wid  = threadIdx.x >> 5;
    const int wm = wid & 1, wn = wid >> 1;
    const int g  = lane >> 2;
    const int t4 = lane & 3;
#pragma unroll
    for (int mf = 0; mf < 4; mf++) {
#pragma unroll
        for (int nf = 0; nf < 4; nf++) {
            const int r0 = rowBase + wm * 64 + mf * 16 + g;
            const int c0 = c1k + wn * 32 + nf * 8 + t4 * 2;
            float b0 = 0.f, b1 = 0.f;
            if (bias) { b0 = bias[c0]; b1 = bias[c0 + 1]; }
            *(uint32_t*)(dst + (size_t)r0 * CDIM + c0) =
                pack2h(alpha * (acc[mf][nf][0] + b0),
                       alpha * (acc[mf][nf][1] + b1));
            *(uint32_t*)(dst + (size_t)(r0 + 8) * CDIM + c0) =
                pack2h(alpha * (acc[mf][nf][2] + b0),
                       alpha * (acc[mf][nf][3] + b1));
        }
    }
}

// output projection: fp32 out = att @ Wo^T + bo
__global__ __launch_bounds__(256, 2)
void gemm_out(const __half* __restrict__ Aa,
              const __half* __restrict__ Wo,
              const float* __restrict__ bo,
              float* __restrict__ Out)
{
    const int rowBase = blockIdx.y * 128;
    const int colBase = blockIdx.x * 128;
    float acc[4][4][4];
    gemm_tile(Aa, Wo, CDIM, rowBase, colBase, acc);

    const int lane = threadIdx.x & 31;
    const int wid  = threadIdx.x >> 5;
    const int wm = wid & 1, wn = wid >> 1;
    const int g  = lane >> 2;
    const int t4 = lane & 3;
#pragma unroll
    for (int mf = 0; mf < 4; mf++) {
#pragma unroll
        for (int nf = 0; nf < 4; nf++) {
            const int r0 = rowBase + wm * 64 + mf * 16 + g;
            const int c0 = colBase + wn * 32 + nf * 8 + t4 * 2;
            const float b0 = bo[c0], b1 = bo[c0 + 1];
            float2 o0, o1;
            o0.x = acc[mf][nf][0] + b0;
            o0.y = acc[mf][nf][1] + b1;
            o1.x = acc[mf][nf][2] + b0;
            o1.y = acc[mf][nf][3] + b1;
            *(float2*)(Out + (size_t)r0 * CDIM + c0)       = o0;
            *(float2*)(Out + (size_t)(r0 + 8) * CDIM + c0) = o1;
        }
    }
}

// ---------------------------------------------------------------------------
// Block-local attention on HMMA. q,k,v,P all single fp16.
// smem: q@0 (16K), k@16K (16K), vT@32K (two [64][64] tiles) = 48 KB.
// ---------------------------------------------------------------------------
#define ATT_SMEM (48 * 1024 + 1024)

__global__ __launch_bounds__(256)
void block_attn_mma(const __half* __restrict__ Q,
                    const __half* __restrict__ K,
                    const __half* __restrict__ V,
                    __half* __restrict__ Oa)
{
    extern __shared__ char dsm[];
    const uint32_t sb0 = smem_u32(dsm);
    const uint32_t sbase = (sb0 + 1023u) & ~1023u;
    char* dsa = dsm + (sbase - sb0);

    const int tid = threadIdx.x;
    const int wid = tid >> 5;
    const int lane = tid & 31;

    const int idx = blockIdx.x;
    const int h = idx & 15, n = (idx >> 4) & 31, b = idx >> 9;
    const size_t base = ((size_t)b * 4096 + (size_t)n * 128) * 1024 + (size_t)h * 64;

    const uint32_t QS = 0, KS = 16384, VT = 32768;

    for (int i = tid; i < 1024; i += 256) {
        int row = i >> 3;
        int cb = (i & 7) * 16;
        uint32_t sw = swz((uint32_t)(row * 128 + cb));
        size_t ge = base + (size_t)row * 1024 + (cb >> 1);
        cp_async16(sbase + QS + sw, Q + ge);
        cp_async16(sbase + KS + sw, K + ge);
    }
    CP_COMMIT();

    for (int i = tid; i < 1024; i += 256) {
        int j = i >> 3;
        int d0 = (i & 7) * 8;
        size_t ge = base + (size_t)j * 1024 + d0;
        uint4 hv = *(const uint4*)(V + ge);
        const __half* h8 = (const __half*)&hv;
        uint32_t tb = (uint32_t)((j >> 6) * 8192);
        int jl = j & 63;
#pragma unroll
        for (int e = 0; e < 8; e++) {
            uint32_t off = swz((uint32_t)((d0 + e) * 128 + jl * 2));
            *(__half*)(dsa + VT + tb + off) = h8[e];
        }
    }
    CP_WAIT(0);
    __syncthreads();

    const uint32_t a_off = swz((uint32_t)((lane & 15) * 128 + ((lane >> 4) << 4)));
    const uint32_t b_off = swz((uint32_t)(
        (((lane >> 4) << 3) + (lane & 7)) * 128 + (((lane >> 3) & 1) << 4)));

    float s[16][4];
#pragma unroll
    for (int nf = 0; nf < 16; nf++)
#pragma unroll
        for (int e = 0; e < 4; e++) s[nf][e] = 0.f;

    const uint32_t aQ = sbase + QS + (uint32_t)(wid * 16 * 128) + a_off;
#pragma unroll
    for (int ks = 0; ks < 4; ks++) {
        const uint32_t kOff = (uint32_t)(ks * 32);
        uint32_t q4[4];
        ldsm4(aQ ^ kOff, q4[0], q4[1], q4[2], q4[3]);
#pragma unroll
        for (int p = 0; p < 8; p++) {
            uint32_t ab = (sbase + KS + (uint32_t)(p * 16 * 128) + b_off) ^ kOff;
            uint32_t bk[2][2];
            ldsm4(ab, bk[0][0], bk[0][1], bk[1][0], bk[1][1]);
            mma16816(s[2 * p],     q4, bk[0]);
            mma16816(s[2 * p + 1], q4, bk[1]);
        }
    }

    float m0 = -CUDART_INF_F, m1 = -CUDART_INF_F;
#pragma unroll
    for (int nf = 0; nf < 16; nf++) {
        m0 = fmaxf(m0, fmaxf(s[nf][0], s[nf][1]));
        m1 = fmaxf(m1, fmaxf(s[nf][2], s[nf][3]));
    }
    m0 = fmaxf(m0, __shfl_xor_sync(0xFFFFFFFFu, m0, 1));
    m0 = fmaxf(m0, __shfl_xor_sync(0xFFFFFFFFu, m0, 2));
    m1 = fmaxf(m1, __shfl_xor_sync(0xFFFFFFFFu, m1, 1));
    m1 = fmaxf(m1, __shfl_xor_sync(0xFFFFFFFFu, m1, 2));

    float sum0 = 0.f, sum1 = 0.f;
#pragma unroll
    for (int nf = 0; nf < 16; nf++) {
        s[nf][0] = __expf(s[nf][0] - m0); sum0 += s[nf][0];
        s[nf][1] = __expf(s[nf][1] - m0); sum0 += s[nf][1];
        s[nf][2] = __expf(s[nf][2] - m1); sum1 += s[nf][2];
        s[nf][3] = __expf(s[nf][3] - m1); sum1 += s[nf][3];
    }
    sum0 += __shfl_xor_sync(0xFFFFFFFFu, sum0, 1);
    sum0 += __shfl_xor_sync(0xFFFFFFFFu, sum0, 2);
    sum1 += __shfl_xor_sync(0xFFFFFFFFu, sum1, 1);
    sum1 += __shfl_xor_sync(0xFFFFFFFFu, sum1, 2);
    const float inv0 = 1.f / sum0;
    const float inv1 = 1.f / sum1;

    // P -> single fp16 fragments (rounding adds ~1.4e-4 incoherent)
    uint32_t ph[16][2];
#pragma unroll
    for (int nf = 0; nf < 16; nf++) {
        ph[nf][0] = pack2h(s[nf][0] * inv0, s[nf][1] * inv0);
        ph[nf][1] = pack2h(s[nf][2] * inv1, s[nf][3] * inv1);
    }

    float o[8][4];
#pragma unroll
    for (int nf = 0; nf < 8; nf++)
#pragma unroll
        for (int e = 0; e < 4; e++) o[nf][e] = 0.f;

#pragma unroll
    for (int ks = 0; ks < 8; ks++) {
        uint32_t pa[4] = { ph[2 * ks][0], ph[2 * ks][1],
                           ph[2 * ks + 1][0], ph[2 * ks + 1][1] };
        const uint32_t tb = sbase + VT + (uint32_t)((ks >> 2) * 8192);
        const uint32_t kOff = (uint32_t)((ks & 3) * 32);
#pragma unroll
        for (int p = 0; p < 4; p++) {
            uint32_t ab = (tb + (uint32_t)(p * 16 * 128) + b_off) ^ kOff;
            uint32_t bv2[2][2];
            ldsm4(ab, bv2[0][0], bv2[0][1], bv2[1][0], bv2[1][1]);
            mma16816(o[2 * p],     pa, bv2[0]);
            mma16816(o[2 * p + 1], pa, bv2[1]);
        }
    }

    const int g = lane >> 2, t4 = lane & 3;
#pragma unroll
    for (int nf = 0; nf < 8; nf++) {
        const int r0 = wid * 16 + g;
        const int c  = nf * 8 + t4 * 2;
        const size_t e0 = base + (size_t)r0 * 1024 + c;
        const size_t e1 = base + (size_t)(r0 + 8) * 1024 + c;
        *(uint32_t*)(Oa + e0) = pack2h(o[nf][0], o[nf][1]);
        *(uint32_t*)(Oa + e1) = pack2h(o[nf][2], o[nf][3]);
    }
}

// ---------------------------------------------------------------------------
extern "C" void kernel_launch(void* const* d_in, const int* in_sizes, int n_in,
                              void* d_out, int out_size)
{
    const float* x  = (const float*)d_in[0];
    const float* Wq = (const float*)d_in[1];
    const float* bq = (const float*)d_in[2];
    const float* Wk = (const float*)d_in[3];
    const float* Wv = (const float*)d_in[4];
    const float* bv = (const float*)d_in[5];
    const float* Wo = (const float*)d_in[6];
    const float* bo = (const float*)d_in[7];
    float* out = (float*)d_out;

    __half *xs, *qs, *ks, *vs, *as, *w;
    cudaGetSymbolAddress((void**)&xs, g_x);
    cudaGetSymbolAddress((void**)&qs, g_q);
    cudaGetSymbolAddress((void**)&ks, g_k);
    cudaGetSymbolAddress((void**)&vs, g_v);
    cudaGetSymbolAddress((void**)&as, g_a);
    cudaGetSymbolAddress((void**)&w,  g_w);

    cudaFuncSetAttribute(gemm_qkv,
                         cudaFuncAttributeMaxDynamicSharedMemorySize, GK_SMEM);
    cudaFuncSetAttribute(gemm_out,
                         cudaFuncAttributeMaxDynamicSharedMemorySize, GK_SMEM);
    cudaFuncSetAttribute(block_attn_mma,
                         cudaFuncAttributeMaxDynamicSharedMemorySize, ATT_SMEM);

    const int NX = M_ROWS * CDIM;
    const int NW = CDIM * CDIM;

    to_fp16<<<NX / 4 / 256, 256>>>(x, xs, NX);
    weights_to_fp16<<<4 * NW / 4 / 256, 256>>>(Wq, Wk, Wv, Wo, w, NW);

    // fused q/k/v projection: N = 3072
    gemm_qkv<<<dim3(24, 128), 256, GK_SMEM>>>(xs, w, bq, bv, qs, ks, vs);

    block_attn_mma<<<2048, 256, ATT_SMEM>>>(qs, ks, vs, as);

    gemm_out<<<dim3(8, 128), 256, GK_SMEM>>>(as, w + 3 * NW, bo, out);
}

// round 11
// speedup vs baseline: 10.0786x; 1.0582x over previous
#include <cuda_runtime.h>
#include <cuda_fp16.h>
#include <math_constants.h>
#include <cstdint>

// ---------------------------------------------------------------------------
// MultiHeadAttention (block-local). All matmuls on HMMA (mma.sync m16n8k16
// fp16, fp32 acc), all operands single fp16. q/k/v fused GEMM (N=3072).
// Attention: V kept natural-layout in smem, PV B-fragments via
// ldmatrix.x4.trans (no scatter-transpose).
// Shapes: B=4, T=4096, C=1024, H=16, HD=64, NBLOCKS=32, BSIZE=128
// ---------------------------------------------------------------------------

#define M_ROWS 16384
#define CDIM   1024
#define QK_SCALE 0.35355339059327376f   // 64^(-0.25)

__device__ __align__(256) __half g_x[M_ROWS * CDIM];
__device__ __align__(256) __half g_q[M_ROWS * CDIM];
__device__ __align__(256) __half g_k[M_ROWS * CDIM];
__device__ __align__(256) __half g_v[M_ROWS * CDIM];
__device__ __align__(256) __half g_a[M_ROWS * CDIM];
__device__ __align__(256) __half g_w[4 * CDIM * CDIM];

// ---------------------------------------------------------------------------
// helpers
// ---------------------------------------------------------------------------
__device__ __forceinline__ uint32_t smem_u32(const void* p) {
    uint32_t a;
    asm("{ .reg .u64 t; cvta.to.shared.u64 t, %1; cvt.u32.u64 %0, t; }"
        : "=r"(a) : "l"(p));
    return a;
}

__device__ __forceinline__ void cp_async16(uint32_t dst, const void* src) {
    asm volatile("cp.async.cg.shared.global [%0], [%1], 16;"
                 :: "r"(dst), "l"(src));
}
#define CP_COMMIT() asm volatile("cp.async.commit_group;" ::: "memory")
#define CP_WAIT(n)  asm volatile("cp.async.wait_group %0;" :: "n"(n) : "memory")

__device__ __forceinline__ void ldsm4(uint32_t addr, uint32_t& r0, uint32_t& r1,
                                      uint32_t& r2, uint32_t& r3) {
    asm volatile("ldmatrix.sync.aligned.m8n8.x4.shared.b16 {%0,%1,%2,%3}, [%4];"
                 : "=r"(r0), "=r"(r1), "=r"(r2), "=r"(r3) : "r"(addr));
}

__device__ __forceinline__ void ldsm4t(uint32_t addr, uint32_t& r0, uint32_t& r1,
                                       uint32_t& r2, uint32_t& r3) {
    asm volatile("ldmatrix.sync.aligned.m8n8.x4.trans.shared.b16 {%0,%1,%2,%3}, [%4];"
                 : "=r"(r0), "=r"(r1), "=r"(r2), "=r"(r3) : "r"(addr));
}

__device__ __forceinline__ void mma16816(float* d, const uint32_t* a,
                                         const uint32_t* b) {
    asm volatile(
        "mma.sync.aligned.m16n8k16.row.col.f32.f16.f16.f32 "
        "{%0,%1,%2,%3}, {%4,%5,%6,%7}, {%8,%9}, {%0,%1,%2,%3};"
        : "+f"(d[0]), "+f"(d[1]), "+f"(d[2]), "+f"(d[3])
        : "r"(a[0]), "r"(a[1]), "r"(a[2]), "r"(a[3]), "r"(b[0]), "r"(b[1]));
}

__device__ __forceinline__ uint32_t swz(uint32_t off) {
    return off ^ ((off >> 3) & 0x70);
}

__device__ __forceinline__ uint32_t pack2h(float a, float b) {
    __half2 H = __floats2half2_rn(a, b);
    return *(uint32_t*)&H;
}

// ---------------------------------------------------------------------------
// conversion kernels
// ---------------------------------------------------------------------------
__global__ void to_fp16(const float* __restrict__ x,
                        __half* __restrict__ h, int n)
{
    int i = (blockIdx.x * 256 + threadIdx.x) * 4;
    if (i >= n) return;
    float4 v = *(const float4*)(x + i);
    *(uint32_t*)(h + i)     = pack2h(v.x, v.y);
    *(uint32_t*)(h + i + 2) = pack2h(v.z, v.w);
}

__global__ void weights_to_fp16(const float* __restrict__ Wq,
                                const float* __restrict__ Wk,
                                const float* __restrict__ Wv,
                                const float* __restrict__ Wo,
                                __half* __restrict__ w, int NW)
{
    int i = (blockIdx.x * 256 + threadIdx.x) * 4;
    int which = i / NW;
    int off = i - which * NW;
    const float* src = (which == 0) ? Wq : (which == 1) ? Wk
                     : (which == 2) ? Wv : Wo;
    float4 v = *(const float4*)(src + off);
    *(uint32_t*)(w + i)     = pack2h(v.x, v.y);
    *(uint32_t*)(w + i + 2) = pack2h(v.z, v.w);
}

// ---------------------------------------------------------------------------
// HMMA fp16 GEMM core: 128x128 CTA tile, 8 warps (64x32), K chunks of 64,
// 3-stage cp.async ring, one __syncthreads per chunk, 2 CTAs/SM.
// Stage layout: A@0 (16K), B@16K (16K).
// Swizzle invariant: per-k-step offset (bits 5-6) applied with XOR (see R3).
// ---------------------------------------------------------------------------
#define GK_STAGE 32768
#define GK_SMEM  (3 * GK_STAGE + 1024)

__device__ __forceinline__ void load_chunk(uint32_t stg, const __half* tA,
                                           const __half* tB,
                                           int K, int k0, int tid)
{
#pragma unroll
    for (int i = 0; i < 4; i++) {
        int s   = tid + i * 256;
        int row = s >> 3;
        int cb  = (s & 7) * 16;
        uint32_t sw = swz((uint32_t)(row * 128 + cb));
        size_t ge = (size_t)row * K + k0 + (cb >> 1);
        cp_async16(stg + sw,         tA + ge);
        cp_async16(stg + 16384 + sw, tB + ge);
    }
    CP_COMMIT();
}

__device__ __forceinline__ void gemm_tile(const __half* A, const __half* Bs,
                                          int K, int rowBase, int colBase,
                                          float acc[4][4][4])
{
    extern __shared__ char dsm[];
    const uint32_t sbase = (smem_u32(dsm) + 1023u) & ~1023u;

    const int tid = threadIdx.x;
    const int wid = tid >> 5;
    const int lane = tid & 31;
    const int wm = wid & 1;
    const int wn = wid >> 1;

    const __half* tA = A  + (size_t)rowBase * K;
    const __half* tB = Bs + (size_t)colBase * K;

#pragma unroll
    for (int mf = 0; mf < 4; mf++)
#pragma unroll
        for (int nf = 0; nf < 4; nf++)
#pragma unroll
            for (int e = 0; e < 4; e++) acc[mf][nf][e] = 0.f;

    const uint32_t a_off = swz((uint32_t)((lane & 15) * 128 + ((lane >> 4) << 4)));
    const uint32_t b_off = swz((uint32_t)(
        (((lane >> 4) << 3) + (lane & 7)) * 128 + (((lane >> 3) & 1) << 4)));

    const int NCH = K >> 6;      // 16
    load_chunk(sbase,            tA, tB, K, 0, tid);
    load_chunk(sbase + GK_STAGE, tA, tB, K, 64, tid);

    for (int k = 0; k < NCH; k++) {
        if (k + 1 < NCH) CP_WAIT(1); else CP_WAIT(0);
        __syncthreads();

        const uint32_t st = sbase + (uint32_t)(k % 3) * GK_STAGE;
        const uint32_t aBase = st + (uint32_t)(wm * 64 * 128) + a_off;
        const uint32_t bBase = st + 16384 + (uint32_t)(wn * 32 * 128) + b_off;

#pragma unroll
        for (int ks = 0; ks < 4; ks++) {
            const uint32_t kOff = (uint32_t)(ks * 32);   // bits 5-6 -> XOR
            uint32_t bf[4][2];
#pragma unroll
            for (int p = 0; p < 2; p++) {
                uint32_t addr = (bBase + (uint32_t)(p * 16 * 128)) ^ kOff;
                ldsm4(addr, bf[2 * p][0], bf[2 * p][1],
                            bf[2 * p + 1][0], bf[2 * p + 1][1]);
            }
#pragma unroll
            for (int mf = 0; mf < 4; mf++) {
                uint32_t addr = (aBase + (uint32_t)(mf * 16 * 128)) ^ kOff;
                uint32_t a4[4];
                ldsm4(addr, a4[0], a4[1], a4[2], a4[3]);
#pragma unroll
                for (int nf = 0; nf < 4; nf++)
                    mma16816(acc[mf][nf], a4, bf[nf]);
            }
        }

        if (k + 2 < NCH)
            load_chunk(sbase + (uint32_t)((k + 2) % 3) * GK_STAGE,
                       tA, tB, K, (k + 2) * 64, tid);
    }
}

// fused q/k/v projection
__global__ __launch_bounds__(256, 2)
void gemm_qkv(const __half* __restrict__ X,
              const __half* __restrict__ W3,
              const float* __restrict__ bq,
              const float* __restrict__ bv,
              __half* __restrict__ Qo,
              __half* __restrict__ Ko,
              __half* __restrict__ Vo)
{
    const int rowBase = blockIdx.y * 128;
    const int colBase = blockIdx.x * 128;       // 0..2944
    float acc[4][4][4];
    gemm_tile(X, W3, CDIM, rowBase, colBase, acc);

    const int sel = colBase >> 10;
    const int c1k = colBase & 1023;
    __half* dst = (sel == 0) ? Qo : (sel == 1) ? Ko : Vo;
    const float* bias = (sel == 0) ? bq : (sel == 2) ? bv : nullptr;
    const float alpha = (sel == 2) ? 1.0f : QK_SCALE;

    const int lane = threadIdx.x & 31;
    const int wid  = threadIdx.x >> 5;
    const int wm = wid & 1, wn = wid >> 1;
    const int g  = lane >> 2;
    const int t4 = lane & 3;
#pragma unroll
    for (int mf = 0; mf < 4; mf++) {
#pragma unroll
        for (int nf = 0; nf < 4; nf++) {
            const int r0 = rowBase + wm * 64 + mf * 16 + g;
            const int c0 = c1k + wn * 32 + nf * 8 + t4 * 2;
            float b0 = 0.f, b1 = 0.f;
            if (bias) { b0 = bias[c0]; b1 = bias[c0 + 1]; }
            *(uint32_t*)(dst + (size_t)r0 * CDIM + c0) =
                pack2h(alpha * (acc[mf][nf][0] + b0),
                       alpha * (acc[mf][nf][1] + b1));
            *(uint32_t*)(dst + (size_t)(r0 + 8) * CDIM + c0) =
                pack2h(alpha * (acc[mf][nf][2] + b0),
                       alpha * (acc[mf][nf][3] + b1));
        }
    }
}

// output projection: fp32 out = att @ Wo^T + bo
__global__ __launch_bounds__(256, 2)
void gemm_out(const __half* __restrict__ Aa,
              const __half* __restrict__ Wo,
              const float* __restrict__ bo,
              float* __restrict__ Out)
{
    const int rowBase = blockIdx.y * 128;
    const int colBase = blockIdx.x * 128;
    float acc[4][4][4];
    gemm_tile(Aa, Wo, CDIM, rowBase, colBase, acc);

    const int lane = threadIdx.x & 31;
    const int wid  = threadIdx.x >> 5;
    const int wm = wid & 1, wn = wid >> 1;
    const int g  = lane >> 2;
    const int t4 = lane & 3;
#pragma unroll
    for (int mf = 0; mf < 4; mf++) {
#pragma unroll
        for (int nf = 0; nf < 4; nf++) {
            const int r0 = rowBase + wm * 64 + mf * 16 + g;
            const int c0 = colBase + wn * 32 + nf * 8 + t4 * 2;
            const float b0 = bo[c0], b1 = bo[c0 + 1];
            float2 o0, o1;
            o0.x = acc[mf][nf][0] + b0;
            o0.y = acc[mf][nf][1] + b1;
            o1.x = acc[mf][nf][2] + b0;
            o1.y = acc[mf][nf][3] + b1;
            *(float2*)(Out + (size_t)r0 * CDIM + c0)       = o0;
            *(float2*)(Out + (size_t)(r0 + 8) * CDIM + c0) = o1;
        }
    }
}

// ---------------------------------------------------------------------------
// Block-local attention on HMMA. q,k,v,P all single fp16.
// V kept natural [j][d] (128B rows, SW128); PV B-fragments loaded with
// ldmatrix.x4.trans: tile t -> (k-half = t&1, n-half = t>>1), lane&7 = k-row.
// smem: q@0 (16K), k@16K (16K), v@32K (16K) = 48 KB.
// ---------------------------------------------------------------------------
#define ATT_SMEM (48 * 1024 + 1024)

__global__ __launch_bounds__(256)
void block_attn_mma(const __half* __restrict__ Q,
                    const __half* __restrict__ K,
                    const __half* __restrict__ V,
                    __half* __restrict__ Oa)
{
    extern __shared__ char dsm[];
    const uint32_t sbase = (smem_u32(dsm) + 1023u) & ~1023u;

    const int tid = threadIdx.x;
    const int wid = tid >> 5;
    const int lane = tid & 31;

    const int idx = blockIdx.x;
    const int h = idx & 15, n = (idx >> 4) & 31, b = idx >> 9;
    const size_t base = ((size_t)b * 4096 + (size_t)n * 128) * 1024 + (size_t)h * 64;

    const uint32_t QS = 0, KS = 16384, VS = 32768;

    // q, k, v tiles: identical natural layout (128 rows x 128 B, SW128)
    for (int i = tid; i < 1024; i += 256) {
        int row = i >> 3;
        int cb = (i & 7) * 16;
        uint32_t sw = swz((uint32_t)(row * 128 + cb));
        size_t ge = base + (size_t)row * 1024 + (cb >> 1);
        cp_async16(sbase + QS + sw, Q + ge);
        cp_async16(sbase + KS + sw, K + ge);
        cp_async16(sbase + VS + sw, V + ge);
    }
    CP_COMMIT();
    CP_WAIT(0);
    __syncthreads();

    const uint32_t a_off = swz((uint32_t)((lane & 15) * 128 + ((lane >> 4) << 4)));
    const uint32_t b_off = swz((uint32_t)(
        (((lane >> 4) << 3) + (lane & 7)) * 128 + (((lane >> 3) & 1) << 4)));
    // trans B-fragment lane offset for V [j][d]: tile t = lane>>3,
    // j-row = (t&1)*8 + (lane&7), d-byte = (t>>1)*16
    {
    }
    const uint32_t t_ = (uint32_t)(lane >> 3);
    const uint32_t v_off = swz(((t_ & 1u) * 8u + (uint32_t)(lane & 7)) * 128u +
                               (t_ >> 1) * 16u);

    // ---- S = q k^T : warp owns rows [wid*16, wid*16+16)
    float s[16][4];
#pragma unroll
    for (int nf = 0; nf < 16; nf++)
#pragma unroll
        for (int e = 0; e < 4; e++) s[nf][e] = 0.f;

    const uint32_t aQ = sbase + QS + (uint32_t)(wid * 16 * 128) + a_off;
#pragma unroll
    for (int ks = 0; ks < 4; ks++) {
        const uint32_t kOff = (uint32_t)(ks * 32);
        uint32_t q4[4];
        ldsm4(aQ ^ kOff, q4[0], q4[1], q4[2], q4[3]);
#pragma unroll
        for (int p = 0; p < 8; p++) {
            uint32_t ab = (sbase + KS + (uint32_t)(p * 16 * 128) + b_off) ^ kOff;
            uint32_t bk[2][2];
            ldsm4(ab, bk[0][0], bk[0][1], bk[1][0], bk[1][1]);
            mma16816(s[2 * p],     q4, bk[0]);
            mma16816(s[2 * p + 1], q4, bk[1]);
        }
    }

    // ---- softmax in registers
    float m0 = -CUDART_INF_F, m1 = -CUDART_INF_F;
#pragma unroll
    for (int nf = 0; nf < 16; nf++) {
        m0 = fmaxf(m0, fmaxf(s[nf][0], s[nf][1]));
        m1 = fmaxf(m1, fmaxf(s[nf][2], s[nf][3]));
    }
    m0 = fmaxf(m0, __shfl_xor_sync(0xFFFFFFFFu, m0, 1));
    m0 = fmaxf(m0, __shfl_xor_sync(0xFFFFFFFFu, m0, 2));
    m1 = fmaxf(m1, __shfl_xor_sync(0xFFFFFFFFu, m1, 1));
    m1 = fmaxf(m1, __shfl_xor_sync(0xFFFFFFFFu, m1, 2));

    float sum0 = 0.f, sum1 = 0.f;
#pragma unroll
    for (int nf = 0; nf < 16; nf++) {
        s[nf][0] = __expf(s[nf][0] - m0); sum0 += s[nf][0];
        s[nf][1] = __expf(s[nf][1] - m0); sum0 += s[nf][1];
        s[nf][2] = __expf(s[nf][2] - m1); sum1 += s[nf][2];
        s[nf][3] = __expf(s[nf][3] - m1); sum1 += s[nf][3];
    }
    sum0 += __shfl_xor_sync(0xFFFFFFFFu, sum0, 1);
    sum0 += __shfl_xor_sync(0xFFFFFFFFu, sum0, 2);
    sum1 += __shfl_xor_sync(0xFFFFFFFFu, sum1, 1);
    sum1 += __shfl_xor_sync(0xFFFFFFFFu, sum1, 2);
    const float inv0 = 1.f / sum0;
    const float inv1 = 1.f / sum1;

    // P -> single fp16 fragments (D-layout == A-layout for the PV mma)
    uint32_t ph[16][2];
#pragma unroll
    for (int nf = 0; nf < 16; nf++) {
        ph[nf][0] = pack2h(s[nf][0] * inv0, s[nf][1] * inv0);
        ph[nf][1] = pack2h(s[nf][2] * inv1, s[nf][3] * inv1);
    }

    // ---- O = P @ V via trans ldmatrix on natural V
    float o[8][4];
#pragma unroll
    for (int nf = 0; nf < 8; nf++)
#pragma unroll
        for (int e = 0; e < 4; e++) o[nf][e] = 0.f;

#pragma unroll
    for (int ks = 0; ks < 8; ks++) {
        uint32_t pa[4] = { ph[2 * ks][0], ph[2 * ks][1],
                           ph[2 * ks + 1][0], ph[2 * ks + 1][1] };
        const uint32_t vb = sbase + VS + (uint32_t)(ks * 2048) + v_off;
#pragma unroll
        for (int p = 0; p < 4; p++) {
            uint32_t bv2[2][2];
            ldsm4t(vb ^ (uint32_t)(p * 32),
                   bv2[0][0], bv2[0][1], bv2[1][0], bv2[1][1]);
            mma16816(o[2 * p],     pa, bv2[0]);
            mma16816(o[2 * p + 1], pa, bv2[1]);
        }
    }

    // ---- epilogue
    const int g = lane >> 2, t4 = lane & 3;
#pragma unroll
    for (int nf = 0; nf < 8; nf++) {
        const int r0 = wid * 16 + g;
        const int c  = nf * 8 + t4 * 2;
        const size_t e0 = base + (size_t)r0 * 1024 + c;
        const size_t e1 = base + (size_t)(r0 + 8) * 1024 + c;
        *(uint32_t*)(Oa + e0) = pack2h(o[nf][0], o[nf][1]);
        *(uint32_t*)(Oa + e1) = pack2h(o[nf][2], o[nf][3]);
    }
}

// ---------------------------------------------------------------------------
extern "C" void kernel_launch(void* const* d_in, const int* in_sizes, int n_in,
                              void* d_out, int out_size)
{
    const float* x  = (const float*)d_in[0];
    const float* Wq = (const float*)d_in[1];
    const float* bq = (const float*)d_in[2];
    const float* Wk = (const float*)d_in[3];
    const float* Wv = (const float*)d_in[4];
    const float* bv = (const float*)d_in[5];
    const float* Wo = (const float*)d_in[6];
    const float* bo = (const float*)d_in[7];
    float* out = (float*)d_out;

    __half *xs, *qs, *ks, *vs, *as, *w;
    cudaGetSymbolAddress((void**)&xs, g_x);
    cudaGetSymbolAddress((void**)&qs, g_q);
    cudaGetSymbolAddress((void**)&ks, g_k);
    cudaGetSymbolAddress((void**)&vs, g_v);
    cudaGetSymbolAddress((void**)&as, g_a);
    cudaGetSymbolAddress((void**)&w,  g_w);

    cudaFuncSetAttribute(gemm_qkv,
                         cudaFuncAttributeMaxDynamicSharedMemorySize, GK_SMEM);
    cudaFuncSetAttribute(gemm_out,
                         cudaFuncAttributeMaxDynamicSharedMemorySize, GK_SMEM);
    cudaFuncSetAttribute(block_attn_mma,
                         cudaFuncAttributeMaxDynamicSharedMemorySize, ATT_SMEM);

    const int NX = M_ROWS * CDIM;
    const int NW = CDIM * CDIM;

    to_fp16<<<NX / 4 / 256, 256>>>(x, xs, NX);
    weights_to_fp16<<<4 * NW / 4 / 256, 256>>>(Wq, Wk, Wv, Wo, w, NW);

    gemm_qkv<<<dim3(24, 128), 256, GK_SMEM>>>(xs, w, bq, bv, qs, ks, vs);

    block_attn_mma<<<2048, 256, ATT_SMEM>>>(qs, ks, vs, as);

    gemm_out<<<dim3(8, 128), 256, GK_SMEM>>>(as, w + 3 * NW, bo, out);
}